// round 1
// baseline (speedup 1.0000x reference)
#include <cuda_runtime.h>

#define BATCH   32
#define NTOK    3136
#define CDIM    192
#define WSZ     7
#define NWSIDE  8
#define NW      49
#define NHEADS  6
#define DHEAD   32
#define BWIN    2048      // BATCH * NWSIDE * NWSIDE
#define MROWS   100352    // BWIN * NW

// Scratch (device globals — allocation is forbidden)
__device__ float g_xn  [(size_t)MROWS * CDIM];      //  77 MB
__device__ float g_qkv [(size_t)MROWS * 3 * CDIM];  // 231 MB
__device__ float g_attn[(size_t)MROWS * CDIM];      //  77 MB

// ---------------------------------------------------------------------------
// Kernel 1: LayerNorm (beta=0) + window-partition gather.
// One block per source token (b, n); 192 threads (one per channel).
// ---------------------------------------------------------------------------
__global__ __launch_bounds__(192) void ln_kernel(const float* __restrict__ x,
                                                 const float* __restrict__ gamma,
                                                 float* __restrict__ out)
{
    const int r   = blockIdx.x;          // source token index b*3136 + n
    const int tid = threadIdx.x;         // channel

    float v  = x[(size_t)r * CDIM + tid];
    float s  = v;
    float sq = v * v;

    __shared__ float red[12];
    #pragma unroll
    for (int o = 16; o > 0; o >>= 1) {
        s  += __shfl_xor_sync(0xffffffffu, s,  o);
        sq += __shfl_xor_sync(0xffffffffu, sq, o);
    }
    const int warp = tid >> 5, lane = tid & 31;
    if (lane == 0) { red[warp] = s; red[warp + 6] = sq; }
    __syncthreads();
    if (tid < 32) {
        float a = (tid < 6) ? red[tid]     : 0.f;
        float b = (tid < 6) ? red[tid + 6] : 0.f;
        #pragma unroll
        for (int o = 4; o > 0; o >>= 1) {
            a += __shfl_xor_sync(0xffffffffu, a, o);
            b += __shfl_xor_sync(0xffffffffu, b, o);
        }
        if (tid == 0) { red[0] = a; red[1] = b; }
    }
    __syncthreads();

    const float mu  = red[0] * (1.f / CDIM);
    const float var = red[1] * (1.f / CDIM) - mu * mu;
    const float inv = rsqrtf(var + 1e-5f);

    // window partition mapping
    const int b_ = r / NTOK;
    const int n  = r % NTOK;
    const int y  = n / 56, xq = n % 56;
    const int wy = y / WSZ, ty = y % WSZ;
    const int wx = xq / WSZ, tx = xq % WSZ;
    const int dest = (b_ * 64 + wy * NWSIDE + wx) * NW + ty * WSZ + tx;

    out[(size_t)dest * CDIM + tid] = (v - mu) * inv * gamma[tid];
}

// ---------------------------------------------------------------------------
// SGEMM: C[M,N] = A[M,K] @ W[N,K]^T + bias.  BM=128, BN=64, BK=16.
// 256 threads, 8x4 register tile. Assumes M%128==0, N%64==0, K%16==0, K%4==0.
// SCATTER epilogue does window-reverse and writes to the final output tensor.
// ---------------------------------------------------------------------------
template<bool SCATTER>
__global__ __launch_bounds__(256) void gemm128x64(const float* __restrict__ A,
                                                  const float* __restrict__ W,
                                                  const float* __restrict__ bias,
                                                  float* __restrict__ Cout,
                                                  int N, int K)
{
    __shared__ __align__(16) float As[16][128];
    __shared__ __align__(16) float Bs[16][64];

    const int tid = threadIdx.x;
    const int bm  = blockIdx.y * 128;
    const int bn  = blockIdx.x * 64;
    const int tx  = tid & 15;        // 16 col groups of 4
    const int ty  = tid >> 4;        // 16 row groups of 8
    const int lrow = tid >> 2;       // 0..63
    const int lk   = (tid & 3) << 2; // 0,4,8,12

    float acc[8][4];
    #pragma unroll
    for (int i = 0; i < 8; i++)
        #pragma unroll
        for (int j = 0; j < 4; j++) acc[i][j] = 0.f;

    const float* Aptr0 = A + (size_t)(bm + lrow)      * K + lk;
    const float* Aptr1 = A + (size_t)(bm + lrow + 64) * K + lk;
    const float* Wptr  = W + (size_t)(bn + lrow)      * K + lk;

    for (int k0 = 0; k0 < K; k0 += 16) {
        float4 a0 = *(const float4*)(Aptr0 + k0);
        float4 a1 = *(const float4*)(Aptr1 + k0);
        float4 b0 = *(const float4*)(Wptr  + k0);
        As[lk + 0][lrow]      = a0.x; As[lk + 1][lrow]      = a0.y;
        As[lk + 2][lrow]      = a0.z; As[lk + 3][lrow]      = a0.w;
        As[lk + 0][lrow + 64] = a1.x; As[lk + 1][lrow + 64] = a1.y;
        As[lk + 2][lrow + 64] = a1.z; As[lk + 3][lrow + 64] = a1.w;
        Bs[lk + 0][lrow] = b0.x; Bs[lk + 1][lrow] = b0.y;
        Bs[lk + 2][lrow] = b0.z; Bs[lk + 3][lrow] = b0.w;
        __syncthreads();

        #pragma unroll
        for (int k = 0; k < 16; k++) {
            float4 al = *(const float4*)&As[k][ty * 8];
            float4 ah = *(const float4*)&As[k][ty * 8 + 4];
            float4 bv = *(const float4*)&Bs[k][tx * 4];
            acc[0][0] += al.x * bv.x; acc[0][1] += al.x * bv.y; acc[0][2] += al.x * bv.z; acc[0][3] += al.x * bv.w;
            acc[1][0] += al.y * bv.x; acc[1][1] += al.y * bv.y; acc[1][2] += al.y * bv.z; acc[1][3] += al.y * bv.w;
            acc[2][0] += al.z * bv.x; acc[2][1] += al.z * bv.y; acc[2][2] += al.z * bv.z; acc[2][3] += al.z * bv.w;
            acc[3][0] += al.w * bv.x; acc[3][1] += al.w * bv.y; acc[3][2] += al.w * bv.z; acc[3][3] += al.w * bv.w;
            acc[4][0] += ah.x * bv.x; acc[4][1] += ah.x * bv.y; acc[4][2] += ah.x * bv.z; acc[4][3] += ah.x * bv.w;
            acc[5][0] += ah.y * bv.x; acc[5][1] += ah.y * bv.y; acc[5][2] += ah.y * bv.z; acc[5][3] += ah.y * bv.w;
            acc[6][0] += ah.z * bv.x; acc[6][1] += ah.z * bv.y; acc[6][2] += ah.z * bv.z; acc[6][3] += ah.z * bv.w;
            acc[7][0] += ah.w * bv.x; acc[7][1] += ah.w * bv.y; acc[7][2] += ah.w * bv.z; acc[7][3] += ah.w * bv.w;
        }
        __syncthreads();
    }

    const float4 bb = *(const float4*)&bias[bn + tx * 4];

    #pragma unroll
    for (int i = 0; i < 8; i++) {
        const int row = bm + ty * 8 + i;
        float4 o;
        o.x = acc[i][0] + bb.x; o.y = acc[i][1] + bb.y;
        o.z = acc[i][2] + bb.z; o.w = acc[i][3] + bb.w;
        if (SCATTER) {
            // window reverse: (bw, t) -> (b, n)
            const int bw = row / NW, t = row % NW;
            const int b_ = bw >> 6, w = bw & 63;
            const int wy = w >> 3, wx = w & 7;
            const int tty = t / WSZ, ttx = t % WSZ;
            const int n = (wy * WSZ + tty) * 56 + wx * WSZ + ttx;
            *(float4*)&Cout[((size_t)b_ * NTOK + n) * CDIM + bn + tx * 4] = o;
        } else {
            *(float4*)&Cout[(size_t)row * N + bn + tx * 4] = o;
        }
    }
}

// ---------------------------------------------------------------------------
// Kernel 3: per-(window, head) attention. 49 tokens, d=32, fully SMEM-resident.
// Relative position bias index computed inline.
// ---------------------------------------------------------------------------
__global__ __launch_bounds__(256) void attn_kernel(const float* __restrict__ qkv,
                                                   const float* __restrict__ rpb,
                                                   float* __restrict__ out)
{
    __shared__ __align__(16) float qs[NW][DHEAD];
    __shared__ __align__(16) float ks[NW][DHEAD];
    __shared__ __align__(16) float vs[NW][DHEAD];
    __shared__ float S[NW][NW];

    const int bw  = blockIdx.x;
    const int h   = blockIdx.y;
    const int tid = threadIdx.x;
    const float scale = 0.17677669529663687f;   // 32^-0.5

    const size_t base = (size_t)bw * NW * (3 * CDIM) + h * DHEAD;
    for (int idx = tid; idx < NW * DHEAD; idx += 256) {
        const int t = idx >> 5, dd = idx & 31;
        const size_t p = base + (size_t)t * (3 * CDIM) + dd;
        qs[t][dd] = qkv[p] * scale;
        ks[t][dd] = qkv[p + CDIM];
        vs[t][dd] = qkv[p + 2 * CDIM];
    }
    __syncthreads();

    for (int idx = tid; idx < NW * NW; idx += 256) {
        const int i = idx / NW, j = idx % NW;
        const float4* qi = (const float4*)qs[i];
        const float4* kj = (const float4*)ks[j];
        float acc = 0.f;
        #pragma unroll
        for (int kk = 0; kk < 8; kk++) {
            float4 a = qi[kk], b = kj[kk];
            acc += a.x * b.x + a.y * b.y + a.z * b.z + a.w * b.w;
        }
        const int yi = i / WSZ, xi = i % WSZ;
        const int yj = j / WSZ, xj = j % WSZ;
        const int bidx = ((yi - yj + 6) * 13 + (xi - xj + 6)) * NHEADS + h;
        S[i][j] = acc + rpb[bidx];
    }
    __syncthreads();

    if (tid < NW) {
        float m = -1e30f;
        #pragma unroll
        for (int j = 0; j < NW; j++) m = fmaxf(m, S[tid][j]);
        float s = 0.f;
        #pragma unroll
        for (int j = 0; j < NW; j++) { float e = __expf(S[tid][j] - m); S[tid][j] = e; s += e; }
        const float inv = 1.f / s;
        #pragma unroll
        for (int j = 0; j < NW; j++) S[tid][j] *= inv;
    }
    __syncthreads();

    for (int idx = tid; idx < NW * DHEAD; idx += 256) {
        const int i = idx >> 5, dd = idx & 31;
        float acc = 0.f;
        #pragma unroll
        for (int j = 0; j < NW; j++) acc += S[i][j] * vs[j][dd];
        out[((size_t)bw * NW + i) * CDIM + h * DHEAD + dd] = acc;
    }
}

// ---------------------------------------------------------------------------
extern "C" void kernel_launch(void* const* d_in, const int* in_sizes, int n_in,
                              void* d_out, int out_size)
{
    const float* x      = (const float*)d_in[0];
    const float* gamma  = (const float*)d_in[1];
    const float* rpb    = (const float*)d_in[2];
    const float* qkv_w  = (const float*)d_in[3];
    const float* qkv_b  = (const float*)d_in[4];
    const float* proj_w = (const float*)d_in[5];
    const float* proj_b = (const float*)d_in[6];
    float* out = (float*)d_out;

    float *xn, *qkv, *attn;
    cudaGetSymbolAddress((void**)&xn,   g_xn);
    cudaGetSymbolAddress((void**)&qkv,  g_qkv);
    cudaGetSymbolAddress((void**)&attn, g_attn);

    ln_kernel<<<MROWS, 192>>>(x, gamma, xn);
    gemm128x64<false><<<dim3(3 * CDIM / 64, MROWS / 128), 256>>>(xn, qkv_w, qkv_b, qkv, 3 * CDIM, CDIM);
    attn_kernel<<<dim3(BWIN, NHEADS), 256>>>(qkv, rpb, attn);
    gemm128x64<true><<<dim3(CDIM / 64, MROWS / 128), 256>>>(attn, proj_w, proj_b, out, CDIM, CDIM);
}

// round 3
// speedup vs baseline: 1.8080x; 1.8080x over previous
#include <cuda_runtime.h>
#include <cstdint>

#define BATCH   32
#define NTOK    3136
#define CDIM    192
#define WSZ     7
#define NW      49
#define NHEADS  6
#define DHEAD   32
#define BWIN    2048
#define MROWS   100352

// ---------------------------------------------------------------------------
__device__ float g_xn  [(size_t)MROWS * CDIM];
__device__ float g_qkv [(size_t)MROWS * 3 * CDIM];
__device__ float g_attn[(size_t)MROWS * CDIM];

__device__ __forceinline__ float tf32r(float x) {
    uint32_t u;
    asm("cvt.rna.tf32.f32 %0, %1;" : "=r"(u) : "f"(x));
    return __uint_as_float(u);
}

__device__ __forceinline__ void mma_tf32(float c[4],
                                         uint32_t a0, uint32_t a1, uint32_t a2, uint32_t a3,
                                         uint32_t b0, uint32_t b1) {
    asm volatile("mma.sync.aligned.m16n8k8.row.col.f32.tf32.tf32.f32 "
                 "{%0,%1,%2,%3}, {%4,%5,%6,%7}, {%8,%9}, {%0,%1,%2,%3};"
                 : "+f"(c[0]), "+f"(c[1]), "+f"(c[2]), "+f"(c[3])
                 : "r"(a0), "r"(a1), "r"(a2), "r"(a3), "r"(b0), "r"(b1));
}

// ---------------------------------------------------------------------------
// Kernel 1: LayerNorm + window-partition gather.
// ---------------------------------------------------------------------------
__global__ __launch_bounds__(192) void ln_kernel(const float* __restrict__ x,
                                                 const float* __restrict__ gamma,
                                                 float* __restrict__ out)
{
    const int r   = blockIdx.x;
    const int tid = threadIdx.x;

    float v  = x[(size_t)r * CDIM + tid];
    float s  = v, sq = v * v;

    __shared__ float red[12];
    #pragma unroll
    for (int o = 16; o > 0; o >>= 1) {
        s  += __shfl_xor_sync(0xffffffffu, s,  o);
        sq += __shfl_xor_sync(0xffffffffu, sq, o);
    }
    const int warp = tid >> 5, lane = tid & 31;
    if (lane == 0) { red[warp] = s; red[warp + 6] = sq; }
    __syncthreads();
    if (tid < 32) {
        float a = (tid < 6) ? red[tid]     : 0.f;
        float b = (tid < 6) ? red[tid + 6] : 0.f;
        #pragma unroll
        for (int o = 4; o > 0; o >>= 1) {
            a += __shfl_xor_sync(0xffffffffu, a, o);
            b += __shfl_xor_sync(0xffffffffu, b, o);
        }
        if (tid == 0) { red[0] = a; red[1] = b; }
    }
    __syncthreads();

    const float mu  = red[0] * (1.f / CDIM);
    const float var = red[1] * (1.f / CDIM) - mu * mu;
    const float inv = rsqrtf(var + 1e-5f);

    const int b_ = r / NTOK;
    const int n  = r % NTOK;
    const int y  = n / 56, xq = n % 56;
    const int wy = y / WSZ, ty = y % WSZ;
    const int wx = xq / WSZ, tx = xq % WSZ;
    const int dest = (b_ * 64 + wy * 8 + wx) * NW + ty * WSZ + tx;

    out[(size_t)dest * CDIM + tid] = (v - mu) * inv * gamma[tid];
}

// ---------------------------------------------------------------------------
// GEMM via mma.sync tf32: C[M,N] = A[M,192] @ W[N,192]^T + bias.
// CTA tile 128x96, 8 warps, warp tile 32x48 (2x6 m16n8k8 tiles), full K=192.
// SMEM rows padded to 196 floats -> conflict-free fragment loads.
// ---------------------------------------------------------------------------
#define APAD 196
#define GEMM_SMEM ((128 + 96) * APAD * 4)

template<bool SCATTER>
__global__ __launch_bounds__(256, 1) void gemm_mma(const float* __restrict__ A,
                                                   const float* __restrict__ W,
                                                   const float* __restrict__ bias,
                                                   float* __restrict__ C,
                                                   int Nfull)
{
    extern __shared__ __align__(16) float sm[];
    float* As = sm;                 // [128][196]
    float* Bs = sm + 128 * APAD;    // [96][196]

    const int tid  = threadIdx.x;
    const int bm   = blockIdx.y * 128;
    const int bn   = blockIdx.x * 96;

    // gmem -> smem with tf32 rounding
    const float* Ab = A + (size_t)bm * CDIM;
    for (int idx = tid; idx < 128 * 48; idx += 256) {
        const int m = idx / 48, k4 = idx % 48;
        float4 v = *(const float4*)(Ab + (size_t)m * CDIM + k4 * 4);
        v.x = tf32r(v.x); v.y = tf32r(v.y); v.z = tf32r(v.z); v.w = tf32r(v.w);
        *(float4*)(As + m * APAD + k4 * 4) = v;
    }
    const float* Wb = W + (size_t)bn * CDIM;
    for (int idx = tid; idx < 96 * 48; idx += 256) {
        const int n = idx / 48, k4 = idx % 48;
        float4 v = *(const float4*)(Wb + (size_t)n * CDIM + k4 * 4);
        v.x = tf32r(v.x); v.y = tf32r(v.y); v.z = tf32r(v.z); v.w = tf32r(v.w);
        *(float4*)(Bs + n * APAD + k4 * 4) = v;
    }
    __syncthreads();

    const int wid  = tid >> 5;
    const int lane = tid & 31;
    const int wm   = (wid >> 1) * 32;      // warp M offset: 0,32,64,96
    const int wn   = (wid & 1) * 48;       // warp N offset: 0,48
    const int gid  = lane >> 2;            // groupID 0..7
    const int ctg  = lane & 3;             // thread-in-group 0..3

    float acc[2][6][4];
    #pragma unroll
    for (int mt = 0; mt < 2; mt++)
        #pragma unroll
        for (int nt = 0; nt < 6; nt++)
            #pragma unroll
            for (int i = 0; i < 4; i++) acc[mt][nt][i] = 0.f;

    const float* aB = As + (wm + gid) * APAD + ctg;
    const float* bB = Bs + (wn + gid) * APAD + ctg;

    #pragma unroll 4
    for (int kk = 0; kk < 24; kk++) {
        const int k0 = kk * 8;
        uint32_t a[2][4], b[6][2];
        #pragma unroll
        for (int mt = 0; mt < 2; mt++) {
            const float* p = aB + mt * 16 * APAD + k0;
            a[mt][0] = __float_as_uint(p[0]);
            a[mt][1] = __float_as_uint(p[8 * APAD]);
            a[mt][2] = __float_as_uint(p[4]);
            a[mt][3] = __float_as_uint(p[8 * APAD + 4]);
        }
        #pragma unroll
        for (int nt = 0; nt < 6; nt++) {
            const float* p = bB + nt * 8 * APAD + k0;
            b[nt][0] = __float_as_uint(p[0]);
            b[nt][1] = __float_as_uint(p[4]);
        }
        #pragma unroll
        for (int mt = 0; mt < 2; mt++)
            #pragma unroll
            for (int nt = 0; nt < 6; nt++)
                mma_tf32(acc[mt][nt], a[mt][0], a[mt][1], a[mt][2], a[mt][3],
                         b[nt][0], b[nt][1]);
    }

    // epilogue: bias + (optional) window-reverse scatter
    #pragma unroll
    for (int mt = 0; mt < 2; mt++) {
        const int row0 = bm + wm + mt * 16 + gid;
        const int row1 = row0 + 8;
        size_t ob0, ob1;
        if (SCATTER) {
            {
                const int bw = row0 / NW, t = row0 % NW;
                const int b_ = bw >> 6, w = bw & 63;
                const int wy = w >> 3, wx = w & 7;
                const int tty = t / WSZ, ttx = t % WSZ;
                ob0 = ((size_t)b_ * NTOK + (wy * WSZ + tty) * 56 + wx * WSZ + ttx) * CDIM;
            }
            {
                const int bw = row1 / NW, t = row1 % NW;
                const int b_ = bw >> 6, w = bw & 63;
                const int wy = w >> 3, wx = w & 7;
                const int tty = t / WSZ, ttx = t % WSZ;
                ob1 = ((size_t)b_ * NTOK + (wy * WSZ + tty) * 56 + wx * WSZ + ttx) * CDIM;
            }
        } else {
            ob0 = (size_t)row0 * Nfull;
            ob1 = (size_t)row1 * Nfull;
        }
        #pragma unroll
        for (int nt = 0; nt < 6; nt++) {
            const int n0 = bn + wn + nt * 8 + ctg * 2;
            const float2 bb = *(const float2*)(bias + n0);
            float2 o0, o1;
            o0.x = acc[mt][nt][0] + bb.x; o0.y = acc[mt][nt][1] + bb.y;
            o1.x = acc[mt][nt][2] + bb.x; o1.y = acc[mt][nt][3] + bb.y;
            *(float2*)(C + ob0 + n0) = o0;
            *(float2*)(C + ob1 + n0) = o1;
        }
    }
}

// ---------------------------------------------------------------------------
// Kernel 3: attention, one block per window, 384 threads (6 heads x 64).
// ---------------------------------------------------------------------------
#define ATT_QOFF 0
#define ATT_KOFF 9408
#define ATT_VOFF 18816
#define ATT_SOFF 28224
#define ATT_ROFF 44688
#define ATT_SMEM ((44688 + 1016) * 4)

__global__ __launch_bounds__(384, 1) void attn_kernel(const float* __restrict__ qkv,
                                                      const float* __restrict__ rpb,
                                                      float* __restrict__ out)
{
    extern __shared__ __align__(16) float smf[];
    const int bw  = blockIdx.x;
    const int tid = threadIdx.x;
    const int h   = tid >> 6;
    const int t   = tid & 63;
    const float scale = 0.17677669529663687f;

    const size_t base = (size_t)bw * NW * (3 * CDIM);
    for (int idx = tid; idx < NW * 144; idx += 384) {
        const int tok = idx / 144, rem = idx % 144;
        const int which = rem / 48, col4 = rem % 48;
        const int hh = col4 >> 3, d4 = col4 & 7;
        float4 v = *(const float4*)(qkv + base + (size_t)tok * (3 * CDIM) + which * CDIM + hh * DHEAD + d4 * 4);
        const int dst = hh * 1568 + tok * 32 + d4 * 4;
        if (which == 0) { v.x *= scale; v.y *= scale; v.z *= scale; v.w *= scale;
                          *(float4*)(smf + ATT_QOFF + dst) = v; }
        else if (which == 1) *(float4*)(smf + ATT_KOFF + dst) = v;
        else                 *(float4*)(smf + ATT_VOFF + dst) = v;
    }
    for (int idx = tid; idx < 169 * NHEADS; idx += 384) smf[ATT_ROFF + idx] = rpb[idx];
    __syncthreads();

    const int ig = t >> 3, jg = t & 7;
    float* sQ = smf + ATT_QOFF + h * 1568;
    float* sK = smf + ATT_KOFF + h * 1568;
    float* sV = smf + ATT_VOFF + h * 1568;
    float* sS = smf + ATT_SOFF + h * 2744;

    if (ig < 7 && jg < 7) {
        const int i0 = ig * 7, j0 = jg * 7;
        float acc[7][7];
        #pragma unroll
        for (int r = 0; r < 7; r++)
            #pragma unroll
            for (int c = 0; c < 7; c++) acc[r][c] = 0.f;

        #pragma unroll
        for (int k4 = 0; k4 < 8; k4++) {
            float4 qv[7], kv[7];
            #pragma unroll
            for (int r = 0; r < 7; r++) qv[r] = *(const float4*)(sQ + (i0 + r) * 32 + k4 * 4);
            #pragma unroll
            for (int c = 0; c < 7; c++) kv[c] = *(const float4*)(sK + (j0 + c) * 32 + k4 * 4);
            #pragma unroll
            for (int r = 0; r < 7; r++)
                #pragma unroll
                for (int c = 0; c < 7; c++)
                    acc[r][c] += qv[r].x * kv[c].x + qv[r].y * kv[c].y
                               + qv[r].z * kv[c].z + qv[r].w * kv[c].w;
        }
        const float* rb = smf + ATT_ROFF;
        #pragma unroll
        for (int r = 0; r < 7; r++)
            #pragma unroll
            for (int c = 0; c < 7; c++) {
                const int bidx = ((ig - jg + 6) * 13 + (r - c + 6)) * NHEADS + h;
                sS[(i0 + r) * 56 + (j0 + c)] = acc[r][c] + rb[bidx];
            }
    }
    __syncthreads();

    if (tid < NHEADS * NW) {
        const int hh = tid / NW, i = tid % NW;
        float* row = smf + ATT_SOFF + hh * 2744 + i * 56;
        float m = -1e30f;
        #pragma unroll
        for (int j = 0; j < NW; j++) m = fmaxf(m, row[j]);
        float s = 0.f;
        #pragma unroll
        for (int j = 0; j < NW; j++) { float e = __expf(row[j] - m); row[j] = e; s += e; }
        const float inv = 1.f / s;
        #pragma unroll
        for (int j = 0; j < NW; j++) row[j] *= inv;
    }
    __syncthreads();

    if (ig < 7) {
        const int i0 = ig * 7, d0 = jg * 4;
        float4 acc[7];
        #pragma unroll
        for (int r = 0; r < 7; r++) acc[r] = make_float4(0.f, 0.f, 0.f, 0.f);
        for (int j = 0; j < NW; j++) {
            float4 vv = *(const float4*)(sV + j * 32 + d0);
            #pragma unroll
            for (int r = 0; r < 7; r++) {
                const float p = sS[(i0 + r) * 56 + j];
                acc[r].x += p * vv.x; acc[r].y += p * vv.y;
                acc[r].z += p * vv.z; acc[r].w += p * vv.w;
            }
        }
        #pragma unroll
        for (int r = 0; r < 7; r++)
            *(float4*)(out + ((size_t)bw * NW + i0 + r) * CDIM + h * DHEAD + d0) = acc[r];
    }
}

// ---------------------------------------------------------------------------
extern "C" void kernel_launch(void* const* d_in, const int* in_sizes, int n_in,
                              void* d_out, int out_size)
{
    const float* x      = (const float*)d_in[0];
    const float* gamma  = (const float*)d_in[1];
    const float* rpb    = (const float*)d_in[2];
    const float* qkv_w  = (const float*)d_in[3];
    const float* qkv_b  = (const float*)d_in[4];
    const float* proj_w = (const float*)d_in[5];
    const float* proj_b = (const float*)d_in[6];
    float* out = (float*)d_out;

    float *xn, *qkv, *attn;
    cudaGetSymbolAddress((void**)&xn,   g_xn);
    cudaGetSymbolAddress((void**)&qkv,  g_qkv);
    cudaGetSymbolAddress((void**)&attn, g_attn);

    cudaFuncSetAttribute(gemm_mma<false>, cudaFuncAttributeMaxDynamicSharedMemorySize, GEMM_SMEM);
    cudaFuncSetAttribute(gemm_mma<true>,  cudaFuncAttributeMaxDynamicSharedMemorySize, GEMM_SMEM);
    cudaFuncSetAttribute(attn_kernel,     cudaFuncAttributeMaxDynamicSharedMemorySize, ATT_SMEM);

    ln_kernel<<<MROWS, 192>>>(x, gamma, xn);
    gemm_mma<false><<<dim3(6, MROWS / 128), 256, GEMM_SMEM>>>(xn, qkv_w, qkv_b, qkv, 3 * CDIM);
    attn_kernel<<<BWIN, 384, ATT_SMEM>>>(qkv, rpb, attn);
    gemm_mma<true><<<dim3(2, MROWS / 128), 256, GEMM_SMEM>>>(attn, proj_w, proj_b, out, CDIM);
}

// round 4
// speedup vs baseline: 2.7671x; 1.5305x over previous
#include <cuda_runtime.h>
#include <cstdint>

#define BATCH   32
#define NTOK    3136
#define CDIM    192
#define WSZ     7
#define NW      49
#define NHEADS  6
#define DHEAD   32
#define BWIN    2048
#define MROWS   100352

// ---------------------------------------------------------------------------
__device__ float g_xn  [(size_t)MROWS * CDIM];
__device__ float g_qkv [(size_t)MROWS * 3 * CDIM];
__device__ float g_attn[(size_t)MROWS * CDIM];
__device__ float g_wq  [3 * CDIM * CDIM];
__device__ float g_wp  [CDIM * CDIM];

__device__ __forceinline__ float tf32r(float x) {
    uint32_t u;
    asm("cvt.rna.tf32.f32 %0, %1;" : "=r"(u) : "f"(x));
    return __uint_as_float(u);
}

__device__ __forceinline__ void mma_tf32(float c[4],
                                         uint32_t a0, uint32_t a1, uint32_t a2, uint32_t a3,
                                         uint32_t b0, uint32_t b1) {
    asm volatile("mma.sync.aligned.m16n8k8.row.col.f32.tf32.tf32.f32 "
                 "{%0,%1,%2,%3}, {%4,%5,%6,%7}, {%8,%9}, {%0,%1,%2,%3};"
                 : "+f"(c[0]), "+f"(c[1]), "+f"(c[2]), "+f"(c[3])
                 : "r"(a0), "r"(a1), "r"(a2), "r"(a3), "r"(b0), "r"(b1));
}

__device__ __forceinline__ uint32_t smem_u32(const void* p) {
    uint32_t a;
    asm("{ .reg .u64 t; cvta.to.shared.u64 t, %1; cvt.u32.u64 %0, t; }" : "=r"(a) : "l"(p));
    return a;
}
__device__ __forceinline__ void cpa16(uint32_t dst, const void* src) {
    asm volatile("cp.async.cg.shared.global [%0], [%1], 16;" :: "r"(dst), "l"(src));
}
__device__ __forceinline__ void cp_commit() { asm volatile("cp.async.commit_group;"); }
template<int N> __device__ __forceinline__ void cp_wait() {
    asm volatile("cp.async.wait_group %0;" :: "n"(N));
}

// ---------------------------------------------------------------------------
// Weight pre-rounding (tf32) into scratch
// ---------------------------------------------------------------------------
__global__ void wround(const float* __restrict__ s, float* __restrict__ d, int n) {
    int i = blockIdx.x * 256 + threadIdx.x;
    if (i < n) d[i] = tf32r(s[i]);
}

// ---------------------------------------------------------------------------
// Kernel 1: LayerNorm + window-partition gather, tf32-rounded output.
// ---------------------------------------------------------------------------
__global__ __launch_bounds__(192) void ln_kernel(const float* __restrict__ x,
                                                 const float* __restrict__ gamma,
                                                 float* __restrict__ out)
{
    const int r   = blockIdx.x;
    const int tid = threadIdx.x;

    float v  = x[(size_t)r * CDIM + tid];
    float s  = v, sq = v * v;

    __shared__ float red[12];
    #pragma unroll
    for (int o = 16; o > 0; o >>= 1) {
        s  += __shfl_xor_sync(0xffffffffu, s,  o);
        sq += __shfl_xor_sync(0xffffffffu, sq, o);
    }
    const int warp = tid >> 5, lane = tid & 31;
    if (lane == 0) { red[warp] = s; red[warp + 6] = sq; }
    __syncthreads();
    if (tid < 32) {
        float a = (tid < 6) ? red[tid]     : 0.f;
        float b = (tid < 6) ? red[tid + 6] : 0.f;
        #pragma unroll
        for (int o = 4; o > 0; o >>= 1) {
            a += __shfl_xor_sync(0xffffffffu, a, o);
            b += __shfl_xor_sync(0xffffffffu, b, o);
        }
        if (tid == 0) { red[0] = a; red[1] = b; }
    }
    __syncthreads();

    const float mu  = red[0] * (1.f / CDIM);
    const float var = red[1] * (1.f / CDIM) - mu * mu;
    const float inv = rsqrtf(var + 1e-5f);

    const int b_ = r / NTOK;
    const int n  = r % NTOK;
    const int y  = n / 56, xq = n % 56;
    const int wy = y / WSZ, ty = y % WSZ;
    const int wx = xq / WSZ, tx = xq % WSZ;
    const int dest = (b_ * 64 + wy * 8 + wx) * NW + ty * WSZ + tx;

    out[(size_t)dest * CDIM + tid] = tf32r((v - mu) * inv * gamma[tid]);
}

// ---------------------------------------------------------------------------
// GEMM via mma.sync tf32, cp.async double-buffered, BK=32.
// CTA 128x96, 8 warps (warp tile 32x48). Inputs pre-rounded to tf32.
// SMEM: A[2][128][36], B[2][96][36] = 63 KB -> 2 CTAs/SM.
// ---------------------------------------------------------------------------
#define BK      32
#define ASTR    36
#define A_STG   (128 * ASTR)
#define B_STG   (96 * ASTR)
#define GEMM_SMEM ((2 * A_STG + 2 * B_STG) * 4)

template<bool SCATTER>
__global__ __launch_bounds__(256, 2) void gemm_mma(const float* __restrict__ A,
                                                   const float* __restrict__ W,
                                                   const float* __restrict__ bias,
                                                   float* __restrict__ C,
                                                   int Nfull)
{
    extern __shared__ __align__(16) float sm[];
    float* As = sm;                    // [2][128][36]
    float* Bs = sm + 2 * A_STG;        // [2][96][36]
    const uint32_t As_u = smem_u32(As);
    const uint32_t Bs_u = smem_u32(Bs);

    const int tid = threadIdx.x;
    const int bm  = blockIdx.y * 128;
    const int bn  = blockIdx.x * 96;

    const float* Ab = A + (size_t)bm * CDIM;
    const float* Wb = W + (size_t)bn * CDIM;

    // async copy of one K-chunk into stage s
    auto copy_stage = [&](int s, int kc) {
        const int k0 = kc * BK;
        #pragma unroll
        for (int i = 0; i < 4; i++) {
            const int idx = tid + i * 256;           // 0..1023
            const int row = idx >> 3, c4 = idx & 7;
            cpa16(As_u + (s * A_STG + row * ASTR + c4 * 4) * 4,
                  Ab + (size_t)row * CDIM + k0 + c4 * 4);
        }
        #pragma unroll
        for (int i = 0; i < 3; i++) {
            const int idx = tid + i * 256;           // 0..767
            const int row = idx >> 3, c4 = idx & 7;
            cpa16(Bs_u + (s * B_STG + row * ASTR + c4 * 4) * 4,
                  Wb + (size_t)row * CDIM + k0 + c4 * 4);
        }
    };

    const int wid  = tid >> 5;
    const int lane = tid & 31;
    const int wm   = (wid >> 1) * 32;
    const int wn   = (wid & 1) * 48;
    const int gid  = lane >> 2;
    const int ctg  = lane & 3;

    float acc[2][6][4];
    #pragma unroll
    for (int mt = 0; mt < 2; mt++)
        #pragma unroll
        for (int nt = 0; nt < 6; nt++)
            #pragma unroll
            for (int i = 0; i < 4; i++) acc[mt][nt][i] = 0.f;

    copy_stage(0, 0);
    cp_commit();

    #pragma unroll
    for (int kk = 0; kk < 6; kk++) {
        if (kk < 5) { copy_stage((kk + 1) & 1, kk + 1); cp_commit(); }
        if (kk < 5) cp_wait<1>(); else cp_wait<0>();
        __syncthreads();

        const float* aB = As + (kk & 1) * A_STG + (wm + gid) * ASTR + ctg;
        const float* bB = Bs + (kk & 1) * B_STG + (wn + gid) * ASTR + ctg;

        #pragma unroll
        for (int ks = 0; ks < 4; ks++) {
            const int k0 = ks * 8;
            uint32_t a[2][4], b[6][2];
            #pragma unroll
            for (int mt = 0; mt < 2; mt++) {
                const float* p = aB + mt * 16 * ASTR + k0;
                a[mt][0] = __float_as_uint(p[0]);
                a[mt][1] = __float_as_uint(p[8 * ASTR]);
                a[mt][2] = __float_as_uint(p[4]);
                a[mt][3] = __float_as_uint(p[8 * ASTR + 4]);
            }
            #pragma unroll
            for (int nt = 0; nt < 6; nt++) {
                const float* p = bB + nt * 8 * ASTR + k0;
                b[nt][0] = __float_as_uint(p[0]);
                b[nt][1] = __float_as_uint(p[4]);
            }
            #pragma unroll
            for (int mt = 0; mt < 2; mt++)
                #pragma unroll
                for (int nt = 0; nt < 6; nt++)
                    mma_tf32(acc[mt][nt], a[mt][0], a[mt][1], a[mt][2], a[mt][3],
                             b[nt][0], b[nt][1]);
        }
        __syncthreads();
    }

    // epilogue: bias + (optional) window-reverse scatter
    #pragma unroll
    for (int mt = 0; mt < 2; mt++) {
        const int row0 = bm + wm + mt * 16 + gid;
        const int row1 = row0 + 8;
        size_t ob0, ob1;
        if (SCATTER) {
            {
                const int bw = row0 / NW, t = row0 % NW;
                const int b_ = bw >> 6, w = bw & 63;
                const int wy = w >> 3, wx = w & 7;
                const int tty = t / WSZ, ttx = t % WSZ;
                ob0 = ((size_t)b_ * NTOK + (wy * WSZ + tty) * 56 + wx * WSZ + ttx) * CDIM;
            }
            {
                const int bw = row1 / NW, t = row1 % NW;
                const int b_ = bw >> 6, w = bw & 63;
                const int wy = w >> 3, wx = w & 7;
                const int tty = t / WSZ, ttx = t % WSZ;
                ob1 = ((size_t)b_ * NTOK + (wy * WSZ + tty) * 56 + wx * WSZ + ttx) * CDIM;
            }
        } else {
            ob0 = (size_t)row0 * Nfull;
            ob1 = (size_t)row1 * Nfull;
        }
        #pragma unroll
        for (int nt = 0; nt < 6; nt++) {
            const int n0 = bn + wn + nt * 8 + ctg * 2;
            const float2 bb = *(const float2*)(bias + n0);
            float2 o0, o1;
            o0.x = acc[mt][nt][0] + bb.x; o0.y = acc[mt][nt][1] + bb.y;
            o1.x = acc[mt][nt][2] + bb.x; o1.y = acc[mt][nt][3] + bb.y;
            *(float2*)(C + ob0 + n0) = o0;
            *(float2*)(C + ob1 + n0) = o1;
        }
    }
}

// ---------------------------------------------------------------------------
// Kernel 3: attention, one block per (window, head), 64 threads.
// SMEM ~30.5 KB -> ~7 blocks/SM. Output tf32-rounded for the proj GEMM.
// ---------------------------------------------------------------------------
#define AH_QOFF 0
#define AH_KOFF 1568
#define AH_VOFF 3136
#define AH_SOFF 4704
#define AH_ROFF 7448
#define AH_SMEM ((7448 + 172) * 4)

__global__ __launch_bounds__(64) void attn_kernel(const float* __restrict__ qkv,
                                                  const float* __restrict__ rpb,
                                                  float* __restrict__ out)
{
    extern __shared__ __align__(16) float smf[];
    const int bw  = blockIdx.x;
    const int h   = blockIdx.y;
    const int tid = threadIdx.x;
    const float scale = 0.17677669529663687f;

    // load q,k,v for this head: 49 tokens x 3 tensors x 8 float4
    const size_t base = (size_t)bw * NW * (3 * CDIM) + h * DHEAD;
    for (int idx = tid; idx < NW * 24; idx += 64) {
        const int tok = idx / 24, rem = idx % 24;
        const int which = rem >> 3, d4 = rem & 7;
        float4 v = *(const float4*)(qkv + base + (size_t)tok * (3 * CDIM) + which * CDIM + d4 * 4);
        const int dst = which * 1568 + tok * 32 + d4 * 4;
        if (which == 0) { v.x *= scale; v.y *= scale; v.z *= scale; v.w *= scale; }
        *(float4*)(smf + dst) = v;
    }
    for (int i = tid; i < 169; i += 64) smf[AH_ROFF + i] = rpb[i * NHEADS + h];
    __syncthreads();

    const int ig = tid >> 3, jg = tid & 7;
    float* sQ = smf + AH_QOFF;
    float* sK = smf + AH_KOFF;
    float* sV = smf + AH_VOFF;
    float* sS = smf + AH_SOFF;

    if (ig < 7 && jg < 7) {
        const int i0 = ig * 7, j0 = jg * 7;
        float acc[7][7];
        #pragma unroll
        for (int r = 0; r < 7; r++)
            #pragma unroll
            for (int c = 0; c < 7; c++) acc[r][c] = 0.f;

        #pragma unroll
        for (int k4 = 0; k4 < 8; k4++) {
            float4 qv[7], kv[7];
            #pragma unroll
            for (int r = 0; r < 7; r++) qv[r] = *(const float4*)(sQ + (i0 + r) * 32 + k4 * 4);
            #pragma unroll
            for (int c = 0; c < 7; c++) kv[c] = *(const float4*)(sK + (j0 + c) * 32 + k4 * 4);
            #pragma unroll
            for (int r = 0; r < 7; r++)
                #pragma unroll
                for (int c = 0; c < 7; c++)
                    acc[r][c] += qv[r].x * kv[c].x + qv[r].y * kv[c].y
                               + qv[r].z * kv[c].z + qv[r].w * kv[c].w;
        }
        const float* rb = smf + AH_ROFF;
        #pragma unroll
        for (int r = 0; r < 7; r++)
            #pragma unroll
            for (int c = 0; c < 7; c++)
                sS[(i0 + r) * 56 + (j0 + c)] = acc[r][c]
                    + rb[(ig - jg + 6) * 13 + (r - c + 6)];
    }
    __syncthreads();

    if (tid < NW) {
        float* row = sS + tid * 56;
        float m = -1e30f;
        #pragma unroll
        for (int j = 0; j < NW; j++) m = fmaxf(m, row[j]);
        float s = 0.f;
        #pragma unroll
        for (int j = 0; j < NW; j++) { float e = __expf(row[j] - m); row[j] = e; s += e; }
        const float inv = 1.f / s;
        #pragma unroll
        for (int j = 0; j < NW; j++) row[j] *= inv;
    }
    __syncthreads();

    if (ig < 7) {
        const int i0 = ig * 7, d0 = jg * 4;
        float4 acc[7];
        #pragma unroll
        for (int r = 0; r < 7; r++) acc[r] = make_float4(0.f, 0.f, 0.f, 0.f);
        for (int j = 0; j < NW; j++) {
            float4 vv = *(const float4*)(sV + j * 32 + d0);
            #pragma unroll
            for (int r = 0; r < 7; r++) {
                const float p = sS[(i0 + r) * 56 + j];
                acc[r].x += p * vv.x; acc[r].y += p * vv.y;
                acc[r].z += p * vv.z; acc[r].w += p * vv.w;
            }
        }
        #pragma unroll
        for (int r = 0; r < 7; r++) {
            float4 o;
            o.x = tf32r(acc[r].x); o.y = tf32r(acc[r].y);
            o.z = tf32r(acc[r].z); o.w = tf32r(acc[r].w);
            *(float4*)(out + ((size_t)bw * NW + i0 + r) * CDIM + h * DHEAD + d0) = o;
        }
    }
}

// ---------------------------------------------------------------------------
extern "C" void kernel_launch(void* const* d_in, const int* in_sizes, int n_in,
                              void* d_out, int out_size)
{
    const float* x      = (const float*)d_in[0];
    const float* gamma  = (const float*)d_in[1];
    const float* rpb    = (const float*)d_in[2];
    const float* qkv_w  = (const float*)d_in[3];
    const float* qkv_b  = (const float*)d_in[4];
    const float* proj_w = (const float*)d_in[5];
    const float* proj_b = (const float*)d_in[6];
    float* out = (float*)d_out;

    float *xn, *qkv, *attn, *wq, *wp;
    cudaGetSymbolAddress((void**)&xn,   g_xn);
    cudaGetSymbolAddress((void**)&qkv,  g_qkv);
    cudaGetSymbolAddress((void**)&attn, g_attn);
    cudaGetSymbolAddress((void**)&wq,   g_wq);
    cudaGetSymbolAddress((void**)&wp,   g_wp);

    cudaFuncSetAttribute(gemm_mma<false>, cudaFuncAttributeMaxDynamicSharedMemorySize, GEMM_SMEM);
    cudaFuncSetAttribute(gemm_mma<true>,  cudaFuncAttributeMaxDynamicSharedMemorySize, GEMM_SMEM);

    wround<<<(3 * CDIM * CDIM + 255) / 256, 256>>>(qkv_w, wq, 3 * CDIM * CDIM);
    wround<<<(CDIM * CDIM + 255) / 256, 256>>>(proj_w, wp, CDIM * CDIM);
    ln_kernel<<<MROWS, 192>>>(x, gamma, xn);
    gemm_mma<false><<<dim3(6, MROWS / 128), 256, GEMM_SMEM>>>(xn, wq, qkv_b, qkv, 3 * CDIM);
    attn_kernel<<<dim3(BWIN, NHEADS), 64, AH_SMEM>>>(qkv, rpb, attn);
    gemm_mma<true><<<dim3(2, MROWS / 128), 256, GEMM_SMEM>>>(attn, wp, proj_b, out, CDIM);
}

// round 5
// speedup vs baseline: 2.9110x; 1.0520x over previous
#include <cuda_runtime.h>
#include <cstdint>

#define BATCH   32
#define NTOK    3136
#define CDIM    192
#define WSZ     7
#define NW      49
#define NHEADS  6
#define DHEAD   32
#define BWIN    2048
#define MROWS   100352

// ---------------------------------------------------------------------------
__device__ float g_xn  [(size_t)MROWS * CDIM];
__device__ float g_qkv [(size_t)MROWS * 3 * CDIM];
__device__ float g_attn[(size_t)MROWS * CDIM];
__device__ float g_wq  [3 * CDIM * CDIM];
__device__ float g_wp  [CDIM * CDIM];

__device__ __forceinline__ float tf32r(float x) {
    uint32_t u;
    asm("cvt.rna.tf32.f32 %0, %1;" : "=r"(u) : "f"(x));
    return __uint_as_float(u);
}

__device__ __forceinline__ void mma_tf32(float c[4],
                                         uint32_t a0, uint32_t a1, uint32_t a2, uint32_t a3,
                                         uint32_t b0, uint32_t b1) {
    asm volatile("mma.sync.aligned.m16n8k8.row.col.f32.tf32.tf32.f32 "
                 "{%0,%1,%2,%3}, {%4,%5,%6,%7}, {%8,%9}, {%0,%1,%2,%3};"
                 : "+f"(c[0]), "+f"(c[1]), "+f"(c[2]), "+f"(c[3])
                 : "r"(a0), "r"(a1), "r"(a2), "r"(a3), "r"(b0), "r"(b1));
}

__device__ __forceinline__ uint32_t smem_u32(const void* p) {
    uint32_t a;
    asm("{ .reg .u64 t; cvta.to.shared.u64 t, %1; cvt.u32.u64 %0, t; }" : "=r"(a) : "l"(p));
    return a;
}
__device__ __forceinline__ void cpa16(uint32_t dst, const void* src) {
    asm volatile("cp.async.cg.shared.global [%0], [%1], 16;" :: "r"(dst), "l"(src));
}
__device__ __forceinline__ void cp_commit() { asm volatile("cp.async.commit_group;"); }
template<int N> __device__ __forceinline__ void cp_wait() {
    asm volatile("cp.async.wait_group %0;" :: "n"(N));
}

// ---------------------------------------------------------------------------
__global__ void wround(const float* __restrict__ s, float* __restrict__ d, int n) {
    int i = blockIdx.x * 256 + threadIdx.x;
    if (i < n) d[i] = tf32r(s[i]);
}

// ---------------------------------------------------------------------------
// Kernel 1: LayerNorm + window-partition gather, tf32-rounded output.
// ---------------------------------------------------------------------------
__global__ __launch_bounds__(192) void ln_kernel(const float* __restrict__ x,
                                                 const float* __restrict__ gamma,
                                                 float* __restrict__ out)
{
    const int r   = blockIdx.x;
    const int tid = threadIdx.x;

    float v  = x[(size_t)r * CDIM + tid];
    float s  = v, sq = v * v;

    __shared__ float red[12];
    #pragma unroll
    for (int o = 16; o > 0; o >>= 1) {
        s  += __shfl_xor_sync(0xffffffffu, s,  o);
        sq += __shfl_xor_sync(0xffffffffu, sq, o);
    }
    const int warp = tid >> 5, lane = tid & 31;
    if (lane == 0) { red[warp] = s; red[warp + 6] = sq; }
    __syncthreads();
    if (tid < 32) {
        float a = (tid < 6) ? red[tid]     : 0.f;
        float b = (tid < 6) ? red[tid + 6] : 0.f;
        #pragma unroll
        for (int o = 4; o > 0; o >>= 1) {
            a += __shfl_xor_sync(0xffffffffu, a, o);
            b += __shfl_xor_sync(0xffffffffu, b, o);
        }
        if (tid == 0) { red[0] = a; red[1] = b; }
    }
    __syncthreads();

    const float mu  = red[0] * (1.f / CDIM);
    const float var = red[1] * (1.f / CDIM) - mu * mu;
    const float inv = rsqrtf(var + 1e-5f);

    const int b_ = r / NTOK;
    const int n  = r % NTOK;
    const int y  = n / 56, xq = n % 56;
    const int wy = y / WSZ, ty = y % WSZ;
    const int wx = xq / WSZ, tx = xq % WSZ;
    const int dest = (b_ * 64 + wy * 8 + wx) * NW + ty * WSZ + tx;

    out[(size_t)dest * CDIM + tid] = tf32r((v - mu) * inv * gamma[tid]);
}

// ---------------------------------------------------------------------------
// GEMM via mma.sync tf32, cp.async double-buffered, BK=32 (unchanged from R4).
// ---------------------------------------------------------------------------
#define BK      32
#define ASTR    36
#define A_STG   (128 * ASTR)
#define B_STG   (96 * ASTR)
#define GEMM_SMEM ((2 * A_STG + 2 * B_STG) * 4)

template<bool SCATTER>
__global__ __launch_bounds__(256, 2) void gemm_mma(const float* __restrict__ A,
                                                   const float* __restrict__ W,
                                                   const float* __restrict__ bias,
                                                   float* __restrict__ C,
                                                   int Nfull)
{
    extern __shared__ __align__(16) float sm[];
    float* As = sm;
    float* Bs = sm + 2 * A_STG;
    const uint32_t As_u = smem_u32(As);
    const uint32_t Bs_u = smem_u32(Bs);

    const int tid = threadIdx.x;
    const int bm  = blockIdx.y * 128;
    const int bn  = blockIdx.x * 96;

    const float* Ab = A + (size_t)bm * CDIM;
    const float* Wb = W + (size_t)bn * CDIM;

    auto copy_stage = [&](int s, int kc) {
        const int k0 = kc * BK;
        #pragma unroll
        for (int i = 0; i < 4; i++) {
            const int idx = tid + i * 256;
            const int row = idx >> 3, c4 = idx & 7;
            cpa16(As_u + (s * A_STG + row * ASTR + c4 * 4) * 4,
                  Ab + (size_t)row * CDIM + k0 + c4 * 4);
        }
        #pragma unroll
        for (int i = 0; i < 3; i++) {
            const int idx = tid + i * 256;
            const int row = idx >> 3, c4 = idx & 7;
            cpa16(Bs_u + (s * B_STG + row * ASTR + c4 * 4) * 4,
                  Wb + (size_t)row * CDIM + k0 + c4 * 4);
        }
    };

    const int wid  = tid >> 5;
    const int lane = tid & 31;
    const int wm   = (wid >> 1) * 32;
    const int wn   = (wid & 1) * 48;
    const int gid  = lane >> 2;
    const int ctg  = lane & 3;

    float acc[2][6][4];
    #pragma unroll
    for (int mt = 0; mt < 2; mt++)
        #pragma unroll
        for (int nt = 0; nt < 6; nt++)
            #pragma unroll
            for (int i = 0; i < 4; i++) acc[mt][nt][i] = 0.f;

    copy_stage(0, 0);
    cp_commit();

    #pragma unroll
    for (int kk = 0; kk < 6; kk++) {
        if (kk < 5) { copy_stage((kk + 1) & 1, kk + 1); cp_commit(); }
        if (kk < 5) cp_wait<1>(); else cp_wait<0>();
        __syncthreads();

        const float* aB = As + (kk & 1) * A_STG + (wm + gid) * ASTR + ctg;
        const float* bB = Bs + (kk & 1) * B_STG + (wn + gid) * ASTR + ctg;

        #pragma unroll
        for (int ks = 0; ks < 4; ks++) {
            const int k0 = ks * 8;
            uint32_t a[2][4], b[6][2];
            #pragma unroll
            for (int mt = 0; mt < 2; mt++) {
                const float* p = aB + mt * 16 * ASTR + k0;
                a[mt][0] = __float_as_uint(p[0]);
                a[mt][1] = __float_as_uint(p[8 * ASTR]);
                a[mt][2] = __float_as_uint(p[4]);
                a[mt][3] = __float_as_uint(p[8 * ASTR + 4]);
            }
            #pragma unroll
            for (int nt = 0; nt < 6; nt++) {
                const float* p = bB + nt * 8 * ASTR + k0;
                b[nt][0] = __float_as_uint(p[0]);
                b[nt][1] = __float_as_uint(p[4]);
            }
            #pragma unroll
            for (int mt = 0; mt < 2; mt++)
                #pragma unroll
                for (int nt = 0; nt < 6; nt++)
                    mma_tf32(acc[mt][nt], a[mt][0], a[mt][1], a[mt][2], a[mt][3],
                             b[nt][0], b[nt][1]);
        }
        __syncthreads();
    }

    #pragma unroll
    for (int mt = 0; mt < 2; mt++) {
        const int row0 = bm + wm + mt * 16 + gid;
        const int row1 = row0 + 8;
        size_t ob0, ob1;
        if (SCATTER) {
            {
                const int bw = row0 / NW, t = row0 % NW;
                const int b_ = bw >> 6, w = bw & 63;
                const int wy = w >> 3, wx = w & 7;
                const int tty = t / WSZ, ttx = t % WSZ;
                ob0 = ((size_t)b_ * NTOK + (wy * WSZ + tty) * 56 + wx * WSZ + ttx) * CDIM;
            }
            {
                const int bw = row1 / NW, t = row1 % NW;
                const int b_ = bw >> 6, w = bw & 63;
                const int wy = w >> 3, wx = w & 7;
                const int tty = t / WSZ, ttx = t % WSZ;
                ob1 = ((size_t)b_ * NTOK + (wy * WSZ + tty) * 56 + wx * WSZ + ttx) * CDIM;
            }
        } else {
            ob0 = (size_t)row0 * Nfull;
            ob1 = (size_t)row1 * Nfull;
        }
        #pragma unroll
        for (int nt = 0; nt < 6; nt++) {
            const int n0 = bn + wn + nt * 8 + ctg * 2;
            const float2 bb = *(const float2*)(bias + n0);
            float2 o0, o1;
            o0.x = acc[mt][nt][0] + bb.x; o0.y = acc[mt][nt][1] + bb.y;
            o1.x = acc[mt][nt][2] + bb.x; o1.y = acc[mt][nt][3] + bb.y;
            *(float2*)(C + ob0 + n0) = o0;
            *(float2*)(C + ob1 + n0) = o1;
        }
    }
}

// ---------------------------------------------------------------------------
// Kernel 3: attention via mma.sync tf32. One block per (window, head),
// 64 threads = 2 warps (rows 0-31 / 32-63 of the 64-padded token dim).
// S = Q K^T in 3xTF32 (near-fp32 logits); PV in 1xTF32 (rna-rounded P, V).
// SMEM (floats): V[56][36]@0, rpb[169]@2016, Qhi/Qlo/Khi/Klo[49][36]@2192,
// S[64][60] overlays the Q/K region after the S-phase.
// ---------------------------------------------------------------------------
#define AT_VOFF 0
#define AT_ROFF 2016
#define AT_QOFF 2192
#define AT_SMEMF 9504

__global__ __launch_bounds__(64) void attn_mma(const float* __restrict__ qkv,
                                               const float* __restrict__ rpb,
                                               float* __restrict__ out)
{
    __shared__ __align__(16) float smf[AT_SMEMF];
    float* sV  = smf + AT_VOFF;          // [56][36], rows 49-55 zeroed
    float* sRp = smf + AT_ROFF;          // [169]
    float* sQh = smf + AT_QOFF;          // [49][36]
    float* sQl = sQh + 1764;
    float* sKh = sQl + 1764;
    float* sKl = sKh + 1764;
    float* sS  = smf + AT_QOFF;          // overlay [64][60]

    const int bw  = blockIdx.x;
    const int h   = blockIdx.y;
    const int tid = threadIdx.x;
    const int warp = tid >> 5, lane = tid & 31;
    const int gid  = lane >> 2, ctg = lane & 3;
    const float scale = 0.17677669529663687f;

    // zero V padding rows 49..55
    for (int i = tid; i < 7 * 36; i += 64) sV[49 * 36 + i] = 0.f;

    // load q,k,v head slices: 49 tok x 3 x 8 float4
    const size_t base = (size_t)bw * NW * (3 * CDIM) + h * DHEAD;
    for (int idx = tid; idx < NW * 24; idx += 64) {
        const int tok = idx / 24, rem = idx % 24;
        const int which = rem >> 3, d4 = rem & 7;
        float4 v = *(const float4*)(qkv + base + (size_t)tok * (3 * CDIM) + which * CDIM + d4 * 4);
        const int o = tok * 36 + d4 * 4;
        if (which == 0) {
            float4 hi, lo;
            float sx = v.x * scale, sy = v.y * scale, sz = v.z * scale, sw = v.w * scale;
            hi.x = tf32r(sx); lo.x = tf32r(sx - hi.x);
            hi.y = tf32r(sy); lo.y = tf32r(sy - hi.y);
            hi.z = tf32r(sz); lo.z = tf32r(sz - hi.z);
            hi.w = tf32r(sw); lo.w = tf32r(sw - hi.w);
            *(float4*)(sQh + o) = hi; *(float4*)(sQl + o) = lo;
        } else if (which == 1) {
            float4 hi, lo;
            hi.x = tf32r(v.x); lo.x = tf32r(v.x - hi.x);
            hi.y = tf32r(v.y); lo.y = tf32r(v.y - hi.y);
            hi.z = tf32r(v.z); lo.z = tf32r(v.z - hi.z);
            hi.w = tf32r(v.w); lo.w = tf32r(v.w - hi.w);
            *(float4*)(sKh + o) = hi; *(float4*)(sKl + o) = lo;
        } else {
            v.x = tf32r(v.x); v.y = tf32r(v.y); v.z = tf32r(v.z); v.w = tf32r(v.w);
            *(float4*)(sV + o) = v;
        }
    }
    for (int i = tid; i < 169; i += 64) sRp[i] = rpb[i * NHEADS + h];
    __syncthreads();

    // ---------------- S phase: 2 M-tiles x 7 N-tiles, 3xTF32 ----------------
    const int r0 = warp * 32;
    float acc[2][7][4];
    #pragma unroll
    for (int mt = 0; mt < 2; mt++)
        #pragma unroll
        for (int nt = 0; nt < 7; nt++)
            #pragma unroll
            for (int i = 0; i < 4; i++) acc[mt][nt][i] = 0.f;

    #pragma unroll
    for (int ks = 0; ks < 4; ks++) {
        const int k0 = ks * 8;
        uint32_t ah[2][4], al[2][4];
        #pragma unroll
        for (int mt = 0; mt < 2; mt++) {
            const float* ph = sQh + (r0 + mt * 16 + gid) * 36 + k0 + ctg;
            const float* pl = sQl + (r0 + mt * 16 + gid) * 36 + k0 + ctg;
            ah[mt][0] = __float_as_uint(ph[0]);
            ah[mt][1] = __float_as_uint(ph[8 * 36]);
            ah[mt][2] = __float_as_uint(ph[4]);
            ah[mt][3] = __float_as_uint(ph[8 * 36 + 4]);
            al[mt][0] = __float_as_uint(pl[0]);
            al[mt][1] = __float_as_uint(pl[8 * 36]);
            al[mt][2] = __float_as_uint(pl[4]);
            al[mt][3] = __float_as_uint(pl[8 * 36 + 4]);
        }
        #pragma unroll
        for (int nt = 0; nt < 7; nt++) {
            const float* ph = sKh + (nt * 8 + gid) * 36 + k0 + ctg;
            const float* pl = sKl + (nt * 8 + gid) * 36 + k0 + ctg;
            const uint32_t bh0 = __float_as_uint(ph[0]);
            const uint32_t bh1 = __float_as_uint(ph[4]);
            const uint32_t bl0 = __float_as_uint(pl[0]);
            const uint32_t bl1 = __float_as_uint(pl[4]);
            #pragma unroll
            for (int mt = 0; mt < 2; mt++) {
                mma_tf32(acc[mt][nt], ah[mt][0], ah[mt][1], ah[mt][2], ah[mt][3], bh0, bh1);
                mma_tf32(acc[mt][nt], ah[mt][0], ah[mt][1], ah[mt][2], ah[mt][3], bl0, bl1);
                mma_tf32(acc[mt][nt], al[mt][0], al[mt][1], al[mt][2], al[mt][3], bh0, bh1);
            }
        }
    }

    // ---------------- bias + mask + softmax (registers + shfl) -------------
    float pout[2][2][7][2];   // [mt][half][nt][c]
    #pragma unroll
    for (int mt = 0; mt < 2; mt++) {
        #pragma unroll
        for (int half = 0; half < 2; half++) {
            const int i = r0 + mt * 16 + half * 8 + gid;
            const bool rowok = (i < NW);
            const int yi = i / 7, xi = i - yi * 7;
            float v[7][2];
            #pragma unroll
            for (int nt = 0; nt < 7; nt++)
                #pragma unroll
                for (int c = 0; c < 2; c++) {
                    const int j = nt * 8 + 2 * ctg + c;
                    float t = acc[mt][nt][half * 2 + c];
                    if (rowok && j < NW) {
                        const int yj = j / 7, xj = j - yj * 7;
                        t += sRp[(yi - yj + 6) * 13 + (xi - xj + 6)];
                    } else {
                        t = rowok ? -1e30f : 0.f;
                    }
                    v[nt][c] = t;
                }
            float m = -1e30f;
            #pragma unroll
            for (int nt = 0; nt < 7; nt++) { m = fmaxf(m, v[nt][0]); m = fmaxf(m, v[nt][1]); }
            m = fmaxf(m, __shfl_xor_sync(0xffffffffu, m, 1));
            m = fmaxf(m, __shfl_xor_sync(0xffffffffu, m, 2));
            float s = 0.f;
            #pragma unroll
            for (int nt = 0; nt < 7; nt++)
                #pragma unroll
                for (int c = 0; c < 2; c++) { float e = __expf(v[nt][c] - m); v[nt][c] = e; s += e; }
            s += __shfl_xor_sync(0xffffffffu, s, 1);
            s += __shfl_xor_sync(0xffffffffu, s, 2);
            const float inv = 1.f / s;
            #pragma unroll
            for (int nt = 0; nt < 7; nt++)
                #pragma unroll
                for (int c = 0; c < 2; c++) pout[mt][half][nt][c] = v[nt][c] * inv;
        }
    }

    __syncthreads();   // everyone done reading Q/K before the S overlay write

    #pragma unroll
    for (int mt = 0; mt < 2; mt++)
        #pragma unroll
        for (int half = 0; half < 2; half++) {
            const int i = r0 + mt * 16 + half * 8 + gid;
            #pragma unroll
            for (int nt = 0; nt < 7; nt++) {
                float2 p2;
                p2.x = tf32r(pout[mt][half][nt][0]);
                p2.y = tf32r(pout[mt][half][nt][1]);
                *(float2*)(sS + i * 60 + nt * 8 + 2 * ctg) = p2;
            }
        }
    __syncthreads();

    // ---------------- PV phase: 2 M-tiles x 4 N-tiles, K=56 ----------------
    float pacc[2][4][4];
    #pragma unroll
    for (int mt = 0; mt < 2; mt++)
        #pragma unroll
        for (int nt = 0; nt < 4; nt++)
            #pragma unroll
            for (int i = 0; i < 4; i++) pacc[mt][nt][i] = 0.f;

    #pragma unroll
    for (int ks = 0; ks < 7; ks++) {
        const int k0 = ks * 8;
        uint32_t a[2][4];
        #pragma unroll
        for (int mt = 0; mt < 2; mt++) {
            const float* p = sS + (r0 + mt * 16 + gid) * 60 + k0 + ctg;
            a[mt][0] = __float_as_uint(p[0]);
            a[mt][1] = __float_as_uint(p[8 * 60]);
            a[mt][2] = __float_as_uint(p[4]);
            a[mt][3] = __float_as_uint(p[8 * 60 + 4]);
        }
        #pragma unroll
        for (int nt = 0; nt < 4; nt++) {
            const float* pv = sV + (k0 + ctg) * 36 + nt * 8 + gid;
            const uint32_t b0 = __float_as_uint(pv[0]);
            const uint32_t b1 = __float_as_uint(pv[4 * 36]);
            #pragma unroll
            for (int mt = 0; mt < 2; mt++)
                mma_tf32(pacc[mt][nt], a[mt][0], a[mt][1], a[mt][2], a[mt][3], b0, b1);
        }
    }

    // store (tf32-rounded for the proj GEMM)
    #pragma unroll
    for (int mt = 0; mt < 2; mt++)
        #pragma unroll
        for (int half = 0; half < 2; half++) {
            const int i = r0 + mt * 16 + half * 8 + gid;
            if (i < NW) {
                float* ob = out + ((size_t)bw * NW + i) * CDIM + h * DHEAD;
                #pragma unroll
                for (int nt = 0; nt < 4; nt++) {
                    float2 o;
                    o.x = tf32r(pacc[mt][nt][half * 2 + 0]);
                    o.y = tf32r(pacc[mt][nt][half * 2 + 1]);
                    *(float2*)(ob + nt * 8 + 2 * ctg) = o;
                }
            }
        }
}

// ---------------------------------------------------------------------------
extern "C" void kernel_launch(void* const* d_in, const int* in_sizes, int n_in,
                              void* d_out, int out_size)
{
    const float* x      = (const float*)d_in[0];
    const float* gamma  = (const float*)d_in[1];
    const float* rpb    = (const float*)d_in[2];
    const float* qkv_w  = (const float*)d_in[3];
    const float* qkv_b  = (const float*)d_in[4];
    const float* proj_w = (const float*)d_in[5];
    const float* proj_b = (const float*)d_in[6];
    float* out = (float*)d_out;

    float *xn, *qkv, *attn, *wq, *wp;
    cudaGetSymbolAddress((void**)&xn,   g_xn);
    cudaGetSymbolAddress((void**)&qkv,  g_qkv);
    cudaGetSymbolAddress((void**)&attn, g_attn);
    cudaGetSymbolAddress((void**)&wq,   g_wq);
    cudaGetSymbolAddress((void**)&wp,   g_wp);

    cudaFuncSetAttribute(gemm_mma<false>, cudaFuncAttributeMaxDynamicSharedMemorySize, GEMM_SMEM);
    cudaFuncSetAttribute(gemm_mma<true>,  cudaFuncAttributeMaxDynamicSharedMemorySize, GEMM_SMEM);

    wround<<<(3 * CDIM * CDIM + 255) / 256, 256>>>(qkv_w, wq, 3 * CDIM * CDIM);
    wround<<<(CDIM * CDIM + 255) / 256, 256>>>(proj_w, wp, CDIM * CDIM);
    ln_kernel<<<MROWS, 192>>>(x, gamma, xn);
    gemm_mma<false><<<dim3(6, MROWS / 128), 256, GEMM_SMEM>>>(xn, wq, qkv_b, qkv, 3 * CDIM);
    attn_mma<<<dim3(BWIN, NHEADS), 64>>>(qkv, rpb, attn);
    gemm_mma<true><<<dim3(2, MROWS / 128), 256, GEMM_SMEM>>>(attn, wp, proj_b, out, CDIM);
}

// round 7
// speedup vs baseline: 4.1313x; 1.4192x over previous
#include <cuda_runtime.h>
#include <cstdint>

#define BATCH   32
#define NTOK    3136
#define CDIM    192
#define WSZ     7
#define NW      49
#define NHEADS  6
#define DHEAD   32
#define BWIN    2048
#define MROWS   100352

// ---------------------------------------------------------------------------
__device__ float g_xn  [(size_t)MROWS * CDIM];
__device__ float g_qkv [(size_t)MROWS * 3 * CDIM];
__device__ float g_attn[(size_t)MROWS * CDIM];
__device__ float g_wq  [3 * CDIM * CDIM];
__device__ float g_wp  [CDIM * CDIM];

__device__ __forceinline__ float tf32r(float x) {
    uint32_t u;
    asm("cvt.rna.tf32.f32 %0, %1;" : "=r"(u) : "f"(x));
    return __uint_as_float(u);
}

__device__ __forceinline__ void mma_tf32(float c[4],
                                         const uint32_t a[4], const uint32_t b[2]) {
    asm volatile("mma.sync.aligned.m16n8k8.row.col.f32.tf32.tf32.f32 "
                 "{%0,%1,%2,%3}, {%4,%5,%6,%7}, {%8,%9}, {%0,%1,%2,%3};"
                 : "+f"(c[0]), "+f"(c[1]), "+f"(c[2]), "+f"(c[3])
                 : "r"(a[0]), "r"(a[1]), "r"(a[2]), "r"(a[3]), "r"(b[0]), "r"(b[1]));
}

__device__ __forceinline__ uint32_t smem_u32(const void* p) {
    uint32_t a;
    asm("{ .reg .u64 t; cvta.to.shared.u64 t, %1; cvt.u32.u64 %0, t; }" : "=r"(a) : "l"(p));
    return a;
}
__device__ __forceinline__ void ldsm_x4(uint32_t r[4], uint32_t a) {
    asm volatile("ldmatrix.sync.aligned.m8n8.x4.shared.b16 {%0,%1,%2,%3}, [%4];"
                 : "=r"(r[0]), "=r"(r[1]), "=r"(r[2]), "=r"(r[3]) : "r"(a));
}
__device__ __forceinline__ void ldsm_x2(uint32_t r[2], uint32_t a) {
    asm volatile("ldmatrix.sync.aligned.m8n8.x2.shared.b16 {%0,%1}, [%2];"
                 : "=r"(r[0]), "=r"(r[1]) : "r"(a));
}
__device__ __forceinline__ void cpa16(uint32_t dst, const void* src) {
    asm volatile("cp.async.cg.shared.global [%0], [%1], 16;" :: "r"(dst), "l"(src));
}
__device__ __forceinline__ void cp_commit() { asm volatile("cp.async.commit_group;"); }
template<int N> __device__ __forceinline__ void cp_wait() {
    asm volatile("cp.async.wait_group %0;" :: "n"(N));
}

// ---------------------------------------------------------------------------
__global__ void wround(const float* __restrict__ s, float* __restrict__ d, int n) {
    int i = blockIdx.x * 256 + threadIdx.x;
    if (i < n) d[i] = tf32r(s[i]);
}

// ---------------------------------------------------------------------------
// Kernel 1: LayerNorm + window-partition gather. Warp per token, 8 tokens/CTA.
// FIXED: 6 channel-strided loads cover all 192 channels (R6 loaded only 96).
// ---------------------------------------------------------------------------
__global__ __launch_bounds__(256) void ln_kernel(const float* __restrict__ x,
                                                 const float* __restrict__ gamma,
                                                 float* __restrict__ out)
{
    const int warp = threadIdx.x >> 5, lane = threadIdx.x & 31;
    const int tok  = blockIdx.x * 8 + warp;

    const float* xr = x + (size_t)tok * CDIM;
    float v[6];
    float s = 0.f, q = 0.f;
    #pragma unroll
    for (int i = 0; i < 6; i++) {
        v[i] = xr[lane + i * 32];
        s += v[i];
        q += v[i] * v[i];
    }
    #pragma unroll
    for (int o = 16; o > 0; o >>= 1) {
        s += __shfl_xor_sync(0xffffffffu, s, o);
        q += __shfl_xor_sync(0xffffffffu, q, o);
    }
    const float mu  = s * (1.f / CDIM);
    const float var = q * (1.f / CDIM) - mu * mu;
    const float inv = rsqrtf(var + 1e-5f);

    const int b_ = tok / NTOK;
    const int n  = tok % NTOK;
    const int y  = n / 56, xq = n % 56;
    const int wy = y / WSZ, ty = y % WSZ;
    const int wx = xq / WSZ, tx = xq % WSZ;
    const int dest = (b_ * 64 + wy * 8 + wx) * NW + ty * WSZ + tx;

    float* o = out + (size_t)dest * CDIM;
    #pragma unroll
    for (int i = 0; i < 6; i++)
        o[lane + i * 32] = tf32r((v[i] - mu) * inv * gamma[lane + i * 32]);
}

// ---------------------------------------------------------------------------
// GEMM via mma.sync tf32 + ldmatrix fragments, 3-stage cp.async, BK=32.
// CTA 128x96, 8 warps, warp tile 32x48. Inputs pre-rounded to tf32.
// ---------------------------------------------------------------------------
#define BK      32
#define ASTR    36
#define A_STG   (128 * ASTR)
#define B_STG   (96 * ASTR)
#define STG_F   (A_STG + B_STG)
#define GEMM_SMEM (3 * STG_F * 4)

template<bool SCATTER>
__global__ __launch_bounds__(256, 2) void gemm_mma(const float* __restrict__ A,
                                                   const float* __restrict__ W,
                                                   const float* __restrict__ bias,
                                                   float* __restrict__ C,
                                                   int Nfull)
{
    extern __shared__ __align__(16) float sm[];
    const uint32_t sm_u = smem_u32(sm);

    const int tid = threadIdx.x;
    const int bm  = blockIdx.y * 128;
    const int bn  = blockIdx.x * 96;

    const float* Ab = A + (size_t)bm * CDIM;
    const float* Wb = W + (size_t)bn * CDIM;

    auto copy_stage = [&](int s, int kc) {
        const int k0 = kc * BK;
        const uint32_t sb = sm_u + s * STG_F * 4;
        #pragma unroll
        for (int i = 0; i < 4; i++) {
            const int idx = tid + i * 256;
            const int row = idx >> 3, c4 = idx & 7;
            cpa16(sb + (row * ASTR + c4 * 4) * 4,
                  Ab + (size_t)row * CDIM + k0 + c4 * 4);
        }
        #pragma unroll
        for (int i = 0; i < 3; i++) {
            const int idx = tid + i * 256;
            const int row = idx >> 3, c4 = idx & 7;
            cpa16(sb + (A_STG + row * ASTR + c4 * 4) * 4,
                  Wb + (size_t)row * CDIM + k0 + c4 * 4);
        }
    };

    const int wid  = tid >> 5;
    const int lane = tid & 31;
    const int wm   = (wid >> 1) * 32;
    const int wn   = (wid & 1) * 48;
    const int gid  = lane >> 2;
    const int ctg  = lane & 3;

    const int a_off = (wm + (lane & 15)) * ASTR + ((lane >> 4) & 1) * 4;
    const int b_off = A_STG + (wn + (lane & 7)) * ASTR + ((lane >> 3) & 1) * 4;

    float acc[2][6][4];
    #pragma unroll
    for (int mt = 0; mt < 2; mt++)
        #pragma unroll
        for (int nt = 0; nt < 6; nt++)
            #pragma unroll
            for (int i = 0; i < 4; i++) acc[mt][nt][i] = 0.f;

    copy_stage(0, 0); cp_commit();
    copy_stage(1, 1); cp_commit();

    #pragma unroll
    for (int kk = 0; kk < 6; kk++) {
        if (kk < 5) cp_wait<1>(); else cp_wait<0>();
        __syncthreads();
        if (kk < 4) { copy_stage((kk + 2) % 3, kk + 2); cp_commit(); }

        const uint32_t sb = sm_u + (kk % 3) * STG_F * 4;
        const uint32_t aA = sb + a_off * 4;
        const uint32_t aB = sb + b_off * 4;

        #pragma unroll
        for (int ks = 0; ks < 4; ks++) {
            const int k0 = ks * 8;
            uint32_t a[2][4], b[6][2];
            ldsm_x4(a[0], aA + k0 * 4);
            ldsm_x4(a[1], aA + (16 * ASTR + k0) * 4);
            #pragma unroll
            for (int nt = 0; nt < 6; nt++)
                ldsm_x2(b[nt], aB + (nt * 8 * ASTR + k0) * 4);
            #pragma unroll
            for (int mt = 0; mt < 2; mt++)
                #pragma unroll
                for (int nt = 0; nt < 6; nt++)
                    mma_tf32(acc[mt][nt], a[mt], b[nt]);
        }
    }

    #pragma unroll
    for (int mt = 0; mt < 2; mt++) {
        const int row0 = bm + wm + mt * 16 + gid;
        const int row1 = row0 + 8;
        size_t ob0, ob1;
        if (SCATTER) {
            {
                const int bw = row0 / NW, t = row0 % NW;
                const int b_ = bw >> 6, w = bw & 63;
                const int wy = w >> 3, wx = w & 7;
                const int tty = t / WSZ, ttx = t % WSZ;
                ob0 = ((size_t)b_ * NTOK + (wy * WSZ + tty) * 56 + wx * WSZ + ttx) * CDIM;
            }
            {
                const int bw = row1 / NW, t = row1 % NW;
                const int b_ = bw >> 6, w = bw & 63;
                const int wy = w >> 3, wx = w & 7;
                const int tty = t / WSZ, ttx = t % WSZ;
                ob1 = ((size_t)b_ * NTOK + (wy * WSZ + tty) * 56 + wx * WSZ + ttx) * CDIM;
            }
        } else {
            ob0 = (size_t)row0 * Nfull;
            ob1 = (size_t)row1 * Nfull;
        }
        #pragma unroll
        for (int nt = 0; nt < 6; nt++) {
            const int n0 = bn + wn + nt * 8 + ctg * 2;
            const float2 bb = *(const float2*)(bias + n0);
            float2 o0, o1;
            o0.x = acc[mt][nt][0] + bb.x; o0.y = acc[mt][nt][1] + bb.y;
            o1.x = acc[mt][nt][2] + bb.x; o1.y = acc[mt][nt][3] + bb.y;
            *(float2*)(C + ob0 + n0) = o0;
            *(float2*)(C + ob1 + n0) = o1;
        }
    }
}

// ---------------------------------------------------------------------------
// Kernel 3: attention via mma.sync tf32 + ldmatrix. Block per (window, head),
// 128 threads = 4 warps, each owning a 16-row M-tile of the 64-padded rows.
// ---------------------------------------------------------------------------
#define AT_VT  0
#define AT_RP  1920
#define AT_QH  2092
#define AT_QL  4396
#define AT_KH  6700
#define AT_KL  8716
#define AT_TOT 10732

__global__ __launch_bounds__(128) void attn_mma(const float* __restrict__ qkv,
                                                const float* __restrict__ rpb,
                                                float* __restrict__ out)
{
    __shared__ __align__(16) float smf[AT_TOT];
    const uint32_t smu = smem_u32(smf);

    const int bw  = blockIdx.x;
    const int h   = blockIdx.y;
    const int tid = threadIdx.x;
    const int warp = tid >> 5, lane = tid & 31;
    const int gid  = lane >> 2, ctg = lane & 3;
    const float scale = 0.17677669529663687f;

    for (int i = tid; i < 32 * 7; i += 128)
        smf[AT_VT + (i / 7) * 60 + 49 + (i % 7)] = 0.f;

    const size_t base = (size_t)bw * NW * (3 * CDIM) + h * DHEAD;
    for (int idx = tid; idx < NW * 24; idx += 128) {
        const int tok = idx / 24, rem = idx % 24;
        const int which = rem >> 3, d4 = rem & 7;
        float4 v = *(const float4*)(qkv + base + (size_t)tok * (3 * CDIM) + which * CDIM + d4 * 4);
        const int o = tok * 36 + d4 * 4;
        if (which == 0) {
            float4 hi, lo;
            float sx = v.x * scale, sy = v.y * scale, sz = v.z * scale, sw = v.w * scale;
            hi.x = tf32r(sx); lo.x = tf32r(sx - hi.x);
            hi.y = tf32r(sy); lo.y = tf32r(sy - hi.y);
            hi.z = tf32r(sz); lo.z = tf32r(sz - hi.z);
            hi.w = tf32r(sw); lo.w = tf32r(sw - hi.w);
            *(float4*)(smf + AT_QH + o) = hi; *(float4*)(smf + AT_QL + o) = lo;
        } else if (which == 1) {
            float4 hi, lo;
            hi.x = tf32r(v.x); lo.x = tf32r(v.x - hi.x);
            hi.y = tf32r(v.y); lo.y = tf32r(v.y - hi.y);
            hi.z = tf32r(v.z); lo.z = tf32r(v.z - hi.z);
            hi.w = tf32r(v.w); lo.w = tf32r(v.w - hi.w);
            *(float4*)(smf + AT_KH + o) = hi; *(float4*)(smf + AT_KL + o) = lo;
        } else {
            smf[AT_VT + (d4 * 4 + 0) * 60 + tok] = tf32r(v.x);
            smf[AT_VT + (d4 * 4 + 1) * 60 + tok] = tf32r(v.y);
            smf[AT_VT + (d4 * 4 + 2) * 60 + tok] = tf32r(v.z);
            smf[AT_VT + (d4 * 4 + 3) * 60 + tok] = tf32r(v.w);
        }
    }
    for (int i = tid; i < 169; i += 128) smf[AT_RP + i] = rpb[i * NHEADS + h];
    __syncthreads();

    const int r0 = warp * 16;
    float acc[7][4];
    #pragma unroll
    for (int nt = 0; nt < 7; nt++)
        #pragma unroll
        for (int i = 0; i < 4; i++) acc[nt][i] = 0.f;

    const uint32_t qh_a = smu + (AT_QH + (r0 + (lane & 15)) * 36 + ((lane >> 4) & 1) * 4) * 4;
    const uint32_t ql_a = qh_a + (AT_QL - AT_QH) * 4;
    const int k_row = (lane & 7) * 36 + ((lane >> 3) & 1) * 4;

    #pragma unroll
    for (int ks = 0; ks < 4; ks++) {
        const int k0 = ks * 8;
        uint32_t ah[4], al[4];
        ldsm_x4(ah, qh_a + k0 * 4);
        ldsm_x4(al, ql_a + k0 * 4);
        #pragma unroll
        for (int nt = 0; nt < 7; nt++) {
            uint32_t bh[2], bl[2];
            ldsm_x2(bh, smu + (AT_KH + nt * 288 + k_row + k0) * 4);
            ldsm_x2(bl, smu + (AT_KL + nt * 288 + k_row + k0) * 4);
            mma_tf32(acc[nt], ah, bh);
            mma_tf32(acc[nt], ah, bl);
            mma_tf32(acc[nt], al, bh);
        }
    }

    float pout[2][7][2];
    #pragma unroll
    for (int half = 0; half < 2; half++) {
        const int i = r0 + half * 8 + gid;
        const bool rowok = (i < NW);
        const int yi = i / 7, xi = i - yi * 7;
        float v[7][2];
        #pragma unroll
        for (int nt = 0; nt < 7; nt++)
            #pragma unroll
            for (int c = 0; c < 2; c++) {
                const int j = nt * 8 + 2 * ctg + c;
                float t = acc[nt][half * 2 + c];
                if (rowok && j < NW) {
                    const int yj = j / 7, xj = j - yj * 7;
                    t += smf[AT_RP + (yi - yj + 6) * 13 + (xi - xj + 6)];
                } else {
                    t = rowok ? -1e30f : 0.f;
                }
                v[nt][c] = t;
            }
        float m = -1e30f;
        #pragma unroll
        for (int nt = 0; nt < 7; nt++) { m = fmaxf(m, v[nt][0]); m = fmaxf(m, v[nt][1]); }
        m = fmaxf(m, __shfl_xor_sync(0xffffffffu, m, 1));
        m = fmaxf(m, __shfl_xor_sync(0xffffffffu, m, 2));
        float s = 0.f;
        #pragma unroll
        for (int nt = 0; nt < 7; nt++)
            #pragma unroll
            for (int c = 0; c < 2; c++) { float e = __expf(v[nt][c] - m); v[nt][c] = e; s += e; }
        s += __shfl_xor_sync(0xffffffffu, s, 1);
        s += __shfl_xor_sync(0xffffffffu, s, 2);
        const float inv = 1.f / s;
        #pragma unroll
        for (int nt = 0; nt < 7; nt++)
            #pragma unroll
            for (int c = 0; c < 2; c++) pout[half][nt][c] = v[nt][c] * inv;
    }

    __syncthreads();

    #pragma unroll
    for (int half = 0; half < 2; half++) {
        const int i = r0 + half * 8 + gid;
        #pragma unroll
        for (int nt = 0; nt < 7; nt++) {
            float2 p2;
            p2.x = tf32r(pout[half][nt][0]);
            p2.y = tf32r(pout[half][nt][1]);
            *(float2*)(smf + AT_QH + i * 60 + nt * 8 + 2 * ctg) = p2;
        }
    }
    __syncthreads();

    float pacc[4][4];
    #pragma unroll
    for (int nt = 0; nt < 4; nt++)
        #pragma unroll
        for (int i = 0; i < 4; i++) pacc[nt][i] = 0.f;

    const uint32_t p_a = smu + (AT_QH + (r0 + (lane & 15)) * 60 + ((lane >> 4) & 1) * 4) * 4;
    const int v_row = (lane & 7) * 60 + ((lane >> 3) & 1) * 4;

    #pragma unroll
    for (int ks = 0; ks < 7; ks++) {
        const int k0 = ks * 8;
        uint32_t a[4];
        ldsm_x4(a, p_a + k0 * 4);
        #pragma unroll
        for (int nt = 0; nt < 4; nt++) {
            uint32_t b[2];
            ldsm_x2(b, smu + (AT_VT + nt * 8 * 60 + v_row + k0) * 4);
            mma_tf32(pacc[nt], a, b);
        }
    }

    #pragma unroll
    for (int half = 0; half < 2; half++) {
        const int i = r0 + half * 8 + gid;
        if (i < NW) {
            float* ob = out + ((size_t)bw * NW + i) * CDIM + h * DHEAD;
            #pragma unroll
            for (int nt = 0; nt < 4; nt++) {
                float2 o;
                o.x = tf32r(pacc[nt][half * 2 + 0]);
                o.y = tf32r(pacc[nt][half * 2 + 1]);
                *(float2*)(ob + nt * 8 + 2 * ctg) = o;
            }
        }
    }
}

// ---------------------------------------------------------------------------
extern "C" void kernel_launch(void* const* d_in, const int* in_sizes, int n_in,
                              void* d_out, int out_size)
{
    const float* x      = (const float*)d_in[0];
    const float* gamma  = (const float*)d_in[1];
    const float* rpb    = (const float*)d_in[2];
    const float* qkv_w  = (const float*)d_in[3];
    const float* qkv_b  = (const float*)d_in[4];
    const float* proj_w = (const float*)d_in[5];
    const float* proj_b = (const float*)d_in[6];
    float* out = (float*)d_out;

    float *xn, *qkv, *attn, *wq, *wp;
    cudaGetSymbolAddress((void**)&xn,   g_xn);
    cudaGetSymbolAddress((void**)&qkv,  g_qkv);
    cudaGetSymbolAddress((void**)&attn, g_attn);
    cudaGetSymbolAddress((void**)&wq,   g_wq);
    cudaGetSymbolAddress((void**)&wp,   g_wp);

    cudaFuncSetAttribute(gemm_mma<false>, cudaFuncAttributeMaxDynamicSharedMemorySize, GEMM_SMEM);
    cudaFuncSetAttribute(gemm_mma<true>,  cudaFuncAttributeMaxDynamicSharedMemorySize, GEMM_SMEM);

    wround<<<(3 * CDIM * CDIM + 255) / 256, 256>>>(qkv_w, wq, 3 * CDIM * CDIM);
    wround<<<(CDIM * CDIM + 255) / 256, 256>>>(proj_w, wp, CDIM * CDIM);
    ln_kernel<<<MROWS / 8, 256>>>(x, gamma, xn);
    gemm_mma<false><<<dim3(6, MROWS / 128), 256, GEMM_SMEM>>>(xn, wq, qkv_b, qkv, 3 * CDIM);
    attn_mma<<<dim3(BWIN, NHEADS), 128>>>(qkv, rpb, attn);
    gemm_mma<true><<<dim3(2, MROWS / 128), 256, GEMM_SMEM>>>(attn, wp, proj_b, out, CDIM);
}

// round 8
// speedup vs baseline: 4.4928x; 1.0875x over previous
#include <cuda_runtime.h>
#include <cuda_bf16.h>
#include <cstdint>

#define BATCH   32
#define NTOK    3136
#define CDIM    192
#define WSZ     7
#define NW      49
#define NHEADS  6
#define DHEAD   32
#define BWIN    2048
#define MROWS   100352

// ---------------------------------------------------------------------------
__device__ float g_xn  [(size_t)MROWS * CDIM];
__device__ float g_qkv [(size_t)MROWS * 3 * CDIM];
__device__ float g_attn[(size_t)MROWS * CDIM];
__device__ float g_wq  [3 * CDIM * CDIM];
__device__ float g_wp  [CDIM * CDIM];

__device__ __forceinline__ float tf32r(float x) {
    uint32_t u;
    asm("cvt.rna.tf32.f32 %0, %1;" : "=r"(u) : "f"(x));
    return __uint_as_float(u);
}

__device__ __forceinline__ void mma_tf32(float c[4],
                                         const uint32_t a[4], const uint32_t b[2]) {
    asm volatile("mma.sync.aligned.m16n8k8.row.col.f32.tf32.tf32.f32 "
                 "{%0,%1,%2,%3}, {%4,%5,%6,%7}, {%8,%9}, {%0,%1,%2,%3};"
                 : "+f"(c[0]), "+f"(c[1]), "+f"(c[2]), "+f"(c[3])
                 : "r"(a[0]), "r"(a[1]), "r"(a[2]), "r"(a[3]), "r"(b[0]), "r"(b[1]));
}
__device__ __forceinline__ void mma_bf16(float c[4],
                                         const uint32_t a[4], const uint32_t b[2]) {
    asm volatile("mma.sync.aligned.m16n8k16.row.col.f32.bf16.bf16.f32 "
                 "{%0,%1,%2,%3}, {%4,%5,%6,%7}, {%8,%9}, {%0,%1,%2,%3};"
                 : "+f"(c[0]), "+f"(c[1]), "+f"(c[2]), "+f"(c[3])
                 : "r"(a[0]), "r"(a[1]), "r"(a[2]), "r"(a[3]), "r"(b[0]), "r"(b[1]));
}

__device__ __forceinline__ uint32_t smem_u32(const void* p) {
    uint32_t a;
    asm("{ .reg .u64 t; cvta.to.shared.u64 t, %1; cvt.u32.u64 %0, t; }" : "=r"(a) : "l"(p));
    return a;
}
__device__ __forceinline__ void ldsm_x4(uint32_t r[4], uint32_t a) {
    asm volatile("ldmatrix.sync.aligned.m8n8.x4.shared.b16 {%0,%1,%2,%3}, [%4];"
                 : "=r"(r[0]), "=r"(r[1]), "=r"(r[2]), "=r"(r[3]) : "r"(a));
}
__device__ __forceinline__ void ldsm_x2(uint32_t r[2], uint32_t a) {
    asm volatile("ldmatrix.sync.aligned.m8n8.x2.shared.b16 {%0,%1}, [%2];"
                 : "=r"(r[0]), "=r"(r[1]) : "r"(a));
}
__device__ __forceinline__ void cpa16(uint32_t dst, const void* src) {
    asm volatile("cp.async.cg.shared.global [%0], [%1], 16;" :: "r"(dst), "l"(src));
}
__device__ __forceinline__ void cp_commit() { asm volatile("cp.async.commit_group;"); }
template<int N> __device__ __forceinline__ void cp_wait() {
    asm volatile("cp.async.wait_group %0;" :: "n"(N));
}

// ---------------------------------------------------------------------------
__global__ void wround(const float* __restrict__ s, float* __restrict__ d, int n) {
    int i = blockIdx.x * 256 + threadIdx.x;
    if (i < n) d[i] = tf32r(s[i]);
}

// ---------------------------------------------------------------------------
// Kernel 1: LayerNorm + window-partition gather. Warp per token, 8 tokens/CTA.
// ---------------------------------------------------------------------------
__global__ __launch_bounds__(256) void ln_kernel(const float* __restrict__ x,
                                                 const float* __restrict__ gamma,
                                                 float* __restrict__ out)
{
    const int warp = threadIdx.x >> 5, lane = threadIdx.x & 31;
    const int tok  = blockIdx.x * 8 + warp;

    const float* xr = x + (size_t)tok * CDIM;
    float v[6];
    float s = 0.f, q = 0.f;
    #pragma unroll
    for (int i = 0; i < 6; i++) {
        v[i] = xr[lane + i * 32];
        s += v[i];
        q += v[i] * v[i];
    }
    #pragma unroll
    for (int o = 16; o > 0; o >>= 1) {
        s += __shfl_xor_sync(0xffffffffu, s, o);
        q += __shfl_xor_sync(0xffffffffu, q, o);
    }
    const float mu  = s * (1.f / CDIM);
    const float var = q * (1.f / CDIM) - mu * mu;
    const float inv = rsqrtf(var + 1e-5f);

    const int b_ = tok / NTOK;
    const int n  = tok % NTOK;
    const int y  = n / 56, xq = n % 56;
    const int wy = y / WSZ, ty = y % WSZ;
    const int wx = xq / WSZ, tx = xq % WSZ;
    const int dest = (b_ * 64 + wy * 8 + wx) * NW + ty * WSZ + tx;

    float* o = out + (size_t)dest * CDIM;
    #pragma unroll
    for (int i = 0; i < 6; i++)
        o[lane + i * 32] = tf32r((v[i] - mu) * inv * gamma[lane + i * 32]);
}

// ---------------------------------------------------------------------------
// GEMM via mma.sync tf32 + ldmatrix, 3-stage cp.async, BK=32 (unchanged R7).
// ---------------------------------------------------------------------------
#define BK      32
#define ASTR    36
#define A_STG   (128 * ASTR)
#define B_STG   (96 * ASTR)
#define STG_F   (A_STG + B_STG)
#define GEMM_SMEM (3 * STG_F * 4)

template<bool SCATTER>
__global__ __launch_bounds__(256, 2) void gemm_mma(const float* __restrict__ A,
                                                   const float* __restrict__ W,
                                                   const float* __restrict__ bias,
                                                   float* __restrict__ C,
                                                   int Nfull)
{
    extern __shared__ __align__(16) float sm[];
    const uint32_t sm_u = smem_u32(sm);

    const int tid = threadIdx.x;
    const int bm  = blockIdx.y * 128;
    const int bn  = blockIdx.x * 96;

    const float* Ab = A + (size_t)bm * CDIM;
    const float* Wb = W + (size_t)bn * CDIM;

    auto copy_stage = [&](int s, int kc) {
        const int k0 = kc * BK;
        const uint32_t sb = sm_u + s * STG_F * 4;
        #pragma unroll
        for (int i = 0; i < 4; i++) {
            const int idx = tid + i * 256;
            const int row = idx >> 3, c4 = idx & 7;
            cpa16(sb + (row * ASTR + c4 * 4) * 4,
                  Ab + (size_t)row * CDIM + k0 + c4 * 4);
        }
        #pragma unroll
        for (int i = 0; i < 3; i++) {
            const int idx = tid + i * 256;
            const int row = idx >> 3, c4 = idx & 7;
            cpa16(sb + (A_STG + row * ASTR + c4 * 4) * 4,
                  Wb + (size_t)row * CDIM + k0 + c4 * 4);
        }
    };

    const int wid  = tid >> 5;
    const int lane = tid & 31;
    const int wm   = (wid >> 1) * 32;
    const int wn   = (wid & 1) * 48;
    const int gid  = lane >> 2;
    const int ctg  = lane & 3;

    const int a_off = (wm + (lane & 15)) * ASTR + ((lane >> 4) & 1) * 4;
    const int b_off = A_STG + (wn + (lane & 7)) * ASTR + ((lane >> 3) & 1) * 4;

    float acc[2][6][4];
    #pragma unroll
    for (int mt = 0; mt < 2; mt++)
        #pragma unroll
        for (int nt = 0; nt < 6; nt++)
            #pragma unroll
            for (int i = 0; i < 4; i++) acc[mt][nt][i] = 0.f;

    copy_stage(0, 0); cp_commit();
    copy_stage(1, 1); cp_commit();

    #pragma unroll
    for (int kk = 0; kk < 6; kk++) {
        if (kk < 5) cp_wait<1>(); else cp_wait<0>();
        __syncthreads();
        if (kk < 4) { copy_stage((kk + 2) % 3, kk + 2); cp_commit(); }

        const uint32_t sb = sm_u + (kk % 3) * STG_F * 4;
        const uint32_t aA = sb + a_off * 4;
        const uint32_t aB = sb + b_off * 4;

        #pragma unroll
        for (int ks = 0; ks < 4; ks++) {
            const int k0 = ks * 8;
            uint32_t a[2][4], b[6][2];
            ldsm_x4(a[0], aA + k0 * 4);
            ldsm_x4(a[1], aA + (16 * ASTR + k0) * 4);
            #pragma unroll
            for (int nt = 0; nt < 6; nt++)
                ldsm_x2(b[nt], aB + (nt * 8 * ASTR + k0) * 4);
            #pragma unroll
            for (int mt = 0; mt < 2; mt++)
                #pragma unroll
                for (int nt = 0; nt < 6; nt++)
                    mma_tf32(acc[mt][nt], a[mt], b[nt]);
        }
    }

    #pragma unroll
    for (int mt = 0; mt < 2; mt++) {
        const int row0 = bm + wm + mt * 16 + gid;
        const int row1 = row0 + 8;
        size_t ob0, ob1;
        if (SCATTER) {
            {
                const int bw = row0 / NW, t = row0 % NW;
                const int b_ = bw >> 6, w = bw & 63;
                const int wy = w >> 3, wx = w & 7;
                const int tty = t / WSZ, ttx = t % WSZ;
                ob0 = ((size_t)b_ * NTOK + (wy * WSZ + tty) * 56 + wx * WSZ + ttx) * CDIM;
            }
            {
                const int bw = row1 / NW, t = row1 % NW;
                const int b_ = bw >> 6, w = bw & 63;
                const int wy = w >> 3, wx = w & 7;
                const int tty = t / WSZ, ttx = t % WSZ;
                ob1 = ((size_t)b_ * NTOK + (wy * WSZ + tty) * 56 + wx * WSZ + ttx) * CDIM;
            }
        } else {
            ob0 = (size_t)row0 * Nfull;
            ob1 = (size_t)row1 * Nfull;
        }
        #pragma unroll
        for (int nt = 0; nt < 6; nt++) {
            const int n0 = bn + wn + nt * 8 + ctg * 2;
            const float2 bb = *(const float2*)(bias + n0);
            float2 o0, o1;
            o0.x = acc[mt][nt][0] + bb.x; o0.y = acc[mt][nt][1] + bb.y;
            o1.x = acc[mt][nt][2] + bb.x; o1.y = acc[mt][nt][3] + bb.y;
            *(float2*)(C + ob0 + n0) = o0;
            *(float2*)(C + ob1 + n0) = o1;
        }
    }
}

// ---------------------------------------------------------------------------
// Kernel 3: attention. Block per (window, head), 128 threads = 4 warps.
// S = Q K^T via 3x-split bf16 m16n8k16; PV via 1x tf32 m16n8k8.
// SMEM floats: Vt[32][60]@0, rpb@1920, @2092: union{ bf16 Qh/Ql[64][40] +
// Kh/Kl[56][40] (9600 bf16) , S fp32 [64][60] }. Total 6892 f = 27.6 KB.
// ---------------------------------------------------------------------------
#define AT_VT   0
#define AT_RP   1920
#define AT_QK   2092
#define AT_TOT  6892
// bf16-element offsets within the QK block
#define BQH 0
#define BQL 2560
#define BKH 5120
#define BKL 7360

__global__ __launch_bounds__(128, 6) void attn_mma(const float* __restrict__ qkv,
                                                   const float* __restrict__ rpb,
                                                   float* __restrict__ out)
{
    __shared__ __align__(16) float smf[AT_TOT];
    const uint32_t smu = smem_u32(smf);
    __nv_bfloat16* bqk = (__nv_bfloat16*)(smf + AT_QK);
    const uint32_t bqk_u = smu + AT_QK * 4;

    const int bw  = blockIdx.x;
    const int h   = blockIdx.y;
    const int tid = threadIdx.x;
    const int warp = tid >> 5, lane = tid & 31;
    const int gid  = lane >> 2, ctg = lane & 3;
    const float scale = 0.17677669529663687f;

    // zero Vt pad columns j = 49..55
    for (int i = tid; i < 32 * 7; i += 128)
        smf[AT_VT + (i / 7) * 60 + 49 + (i % 7)] = 0.f;

    // load q,k,v head slices: 49 tok x {q,k,v} x 8 float4
    const size_t base = (size_t)bw * NW * (3 * CDIM) + h * DHEAD;
    for (int idx = tid; idx < NW * 24; idx += 128) {
        const int tok = idx / 24, rem = idx % 24;
        const int which = rem >> 3, d4 = rem & 7;
        float4 v = *(const float4*)(qkv + base + (size_t)tok * (3 * CDIM) + which * CDIM + d4 * 4);
        const int oe = tok * 40 + d4 * 4;   // bf16-element offset in a [.][40] array
        if (which == 0) {
            float sx = v.x * scale, sy = v.y * scale, sz = v.z * scale, sw = v.w * scale;
            __nv_bfloat16 hx = __float2bfloat16_rn(sx), hy = __float2bfloat16_rn(sy);
            __nv_bfloat16 hz = __float2bfloat16_rn(sz), hw = __float2bfloat16_rn(sw);
            *(__nv_bfloat162*)(bqk + BQH + oe)     = __nv_bfloat162(hx, hy);
            *(__nv_bfloat162*)(bqk + BQH + oe + 2) = __nv_bfloat162(hz, hw);
            *(__nv_bfloat162*)(bqk + BQL + oe) =
                __nv_bfloat162(__float2bfloat16_rn(sx - __bfloat162float(hx)),
                               __float2bfloat16_rn(sy - __bfloat162float(hy)));
            *(__nv_bfloat162*)(bqk + BQL + oe + 2) =
                __nv_bfloat162(__float2bfloat16_rn(sz - __bfloat162float(hz)),
                               __float2bfloat16_rn(sw - __bfloat162float(hw)));
        } else if (which == 1) {
            __nv_bfloat16 hx = __float2bfloat16_rn(v.x), hy = __float2bfloat16_rn(v.y);
            __nv_bfloat16 hz = __float2bfloat16_rn(v.z), hw = __float2bfloat16_rn(v.w);
            *(__nv_bfloat162*)(bqk + BKH + oe)     = __nv_bfloat162(hx, hy);
            *(__nv_bfloat162*)(bqk + BKH + oe + 2) = __nv_bfloat162(hz, hw);
            *(__nv_bfloat162*)(bqk + BKL + oe) =
                __nv_bfloat162(__float2bfloat16_rn(v.x - __bfloat162float(hx)),
                               __float2bfloat16_rn(v.y - __bfloat162float(hy)));
            *(__nv_bfloat162*)(bqk + BKL + oe + 2) =
                __nv_bfloat162(__float2bfloat16_rn(v.z - __bfloat162float(hz)),
                               __float2bfloat16_rn(v.w - __bfloat162float(hw)));
        } else {
            smf[AT_VT + (d4 * 4 + 0) * 60 + tok] = tf32r(v.x);
            smf[AT_VT + (d4 * 4 + 1) * 60 + tok] = tf32r(v.y);
            smf[AT_VT + (d4 * 4 + 2) * 60 + tok] = tf32r(v.z);
            smf[AT_VT + (d4 * 4 + 3) * 60 + tok] = tf32r(v.w);
        }
    }
    for (int i = tid; i < 169; i += 128) smf[AT_RP + i] = rpb[i * NHEADS + h];
    __syncthreads();

    // ---------------- S phase: 2 k16-iters x 7 N-tiles, 3x bf16 -------------
    const int r0 = warp * 16;
    float acc[7][4];
    #pragma unroll
    for (int nt = 0; nt < 7; nt++)
        #pragma unroll
        for (int i = 0; i < 4; i++) acc[nt][i] = 0.f;

    // bf16 ldmatrix addresses (bytes): row stride 80B, k-group 16B
    const uint32_t qh_a = bqk_u + ((r0 + (lane & 15)) * 40 + ((lane >> 4) & 1) * 8) * 2;
    const uint32_t ql_a = qh_a + BQL * 2;
    const int k_row_b = ((lane & 7) * 40 + ((lane >> 3) & 1) * 8) * 2;

    #pragma unroll
    for (int ks = 0; ks < 2; ks++) {
        const int kb = ks * 32;            // 16 elems * 2 bytes
        uint32_t ah[4], al[4];
        ldsm_x4(ah, qh_a + kb);
        ldsm_x4(al, ql_a + kb);
        #pragma unroll
        for (int nt = 0; nt < 7; nt++) {
            uint32_t bh[2], bl[2];
            ldsm_x2(bh, bqk_u + BKH * 2 + nt * 640 + k_row_b + kb);
            ldsm_x2(bl, bqk_u + BKL * 2 + nt * 640 + k_row_b + kb);
            mma_bf16(acc[nt], ah, bh);
            mma_bf16(acc[nt], ah, bl);
            mma_bf16(acc[nt], al, bh);
        }
    }

    __syncthreads();   // all warps done reading Q/K before S overlay writes

    // ---------------- bias + mask + softmax + P store (per half) ------------
    float* sS = smf + AT_QK;               // fp32 [64][60] overlay
    #pragma unroll
    for (int half = 0; half < 2; half++) {
        const int i = r0 + half * 8 + gid;
        const bool rowok = (i < NW);
        const int yi = i / 7, xi = i - yi * 7;
        float v[7][2];
        #pragma unroll
        for (int nt = 0; nt < 7; nt++)
            #pragma unroll
            for (int c = 0; c < 2; c++) {
                const int j = nt * 8 + 2 * ctg + c;
                float t = acc[nt][half * 2 + c];
                if (rowok && j < NW) {
                    const int yj = j / 7, xj = j - yj * 7;
                    t += smf[AT_RP + (yi - yj + 6) * 13 + (xi - xj + 6)];
                } else {
                    t = rowok ? -1e30f : 0.f;
                }
                v[nt][c] = t;
            }
        float m = -1e30f;
        #pragma unroll
        for (int nt = 0; nt < 7; nt++) { m = fmaxf(m, v[nt][0]); m = fmaxf(m, v[nt][1]); }
        m = fmaxf(m, __shfl_xor_sync(0xffffffffu, m, 1));
        m = fmaxf(m, __shfl_xor_sync(0xffffffffu, m, 2));
        float s = 0.f;
        #pragma unroll
        for (int nt = 0; nt < 7; nt++)
            #pragma unroll
            for (int c = 0; c < 2; c++) { float e = __expf(v[nt][c] - m); v[nt][c] = e; s += e; }
        s += __shfl_xor_sync(0xffffffffu, s, 1);
        s += __shfl_xor_sync(0xffffffffu, s, 2);
        const float inv = 1.f / s;
        #pragma unroll
        for (int nt = 0; nt < 7; nt++) {
            float2 p2;
            p2.x = tf32r(v[nt][0] * inv);
            p2.y = tf32r(v[nt][1] * inv);
            *(float2*)(sS + i * 60 + nt * 8 + 2 * ctg) = p2;
        }
    }
    __syncwarp();      // P rows are warp-private; only warp-level visibility needed

    // ---------------- PV phase: 7 k8-iters x 4 N-tiles, tf32 ---------------
    float pacc[4][4];
    #pragma unroll
    for (int nt = 0; nt < 4; nt++)
        #pragma unroll
        for (int i = 0; i < 4; i++) pacc[nt][i] = 0.f;

    const uint32_t p_a = smu + (AT_QK + (r0 + (lane & 15)) * 60 + ((lane >> 4) & 1) * 4) * 4;
    const int v_row = (lane & 7) * 60 + ((lane >> 3) & 1) * 4;

    #pragma unroll
    for (int ks = 0; ks < 7; ks++) {
        const int k0 = ks * 8;
        uint32_t a[4];
        ldsm_x4(a, p_a + k0 * 4);
        #pragma unroll
        for (int nt = 0; nt < 4; nt++) {
            uint32_t b[2];
            ldsm_x2(b, smu + (AT_VT + nt * 8 * 60 + v_row + k0) * 4);
            mma_tf32(pacc[nt], a, b);
        }
    }

    #pragma unroll
    for (int half = 0; half < 2; half++) {
        const int i = r0 + half * 8 + gid;
        if (i < NW) {
            float* ob = out + ((size_t)bw * NW + i) * CDIM + h * DHEAD;
            #pragma unroll
            for (int nt = 0; nt < 4; nt++) {
                float2 o;
                o.x = tf32r(pacc[nt][half * 2 + 0]);
                o.y = tf32r(pacc[nt][half * 2 + 1]);
                *(float2*)(ob + nt * 8 + 2 * ctg) = o;
            }
        }
    }
}

// ---------------------------------------------------------------------------
extern "C" void kernel_launch(void* const* d_in, const int* in_sizes, int n_in,
                              void* d_out, int out_size)
{
    const float* x      = (const float*)d_in[0];
    const float* gamma  = (const float*)d_in[1];
    const float* rpb    = (const float*)d_in[2];
    const float* qkv_w  = (const float*)d_in[3];
    const float* qkv_b  = (const float*)d_in[4];
    const float* proj_w = (const float*)d_in[5];
    const float* proj_b = (const float*)d_in[6];
    float* out = (float*)d_out;

    float *xn, *qkv, *attn, *wq, *wp;
    cudaGetSymbolAddress((void**)&xn,   g_xn);
    cudaGetSymbolAddress((void**)&qkv,  g_qkv);
    cudaGetSymbolAddress((void**)&attn, g_attn);
    cudaGetSymbolAddress((void**)&wq,   g_wq);
    cudaGetSymbolAddress((void**)&wp,   g_wp);

    cudaFuncSetAttribute(gemm_mma<false>, cudaFuncAttributeMaxDynamicSharedMemorySize, GEMM_SMEM);
    cudaFuncSetAttribute(gemm_mma<true>,  cudaFuncAttributeMaxDynamicSharedMemorySize, GEMM_SMEM);

    wround<<<(3 * CDIM * CDIM + 255) / 256, 256>>>(qkv_w, wq, 3 * CDIM * CDIM);
    wround<<<(CDIM * CDIM + 255) / 256, 256>>>(proj_w, wp, CDIM * CDIM);
    ln_kernel<<<MROWS / 8, 256>>>(x, gamma, xn);
    gemm_mma<false><<<dim3(6, MROWS / 128), 256, GEMM_SMEM>>>(xn, wq, qkv_b, qkv, 3 * CDIM);
    attn_mma<<<dim3(BWIN, NHEADS), 128>>>(qkv, rpb, attn);
    gemm_mma<true><<<dim3(2, MROWS / 128), 256, GEMM_SMEM>>>(attn, wp, proj_b, out, CDIM);
}